// round 12
// baseline (speedup 1.0000x reference)
#include <cuda_runtime.h>
#include <cuda_fp16.h>
#include <math.h>
#include <cstdint>

#define BATCH 2
#define NH    8
#define SEQ   4096
#define HD    64
#define WRD   512
#define MTOT  (BATCH*SEQ)     // 8192
#define NQKV  640             // 64 (K) + 64 (V) + 8*64 (Q)
#define NKT   (SEQ/64)        // 64 key tiles

// Q pre-scale: (1/sqrt(64)) * log2(e)  -> scores in log2 domain, exp2 for softmax
#define QSCALE 0.18033688011112042f

// ---------------- scratch (device globals; no allocation allowed) ----------------
__device__ __half g_xh[MTOT*WRD];            // x fp16 [8192,512]
__device__ __half g_WhT[NQKV*WRD];           // packed QKV weight, transposed [n][k] fp16
__device__ __half g_WpT[HD*WRD];             // Wp transposed [n][k] fp16
__device__ float  g_ball[NQKV];              // packed QKV bias fp32
__device__ __half g_Kh[BATCH*SEQ*HD];        // K  [b,t,d] fp16
__device__ __half g_Vth[BATCH*HD*SEQ];       // V^T [b,d,t] fp16
__device__ __half g_Qh[BATCH*NH*SEQ*HD];     // Q  [b,h,s,d] fp16 (pre-scaled)
__device__ __half g_Zch[BATCH*SEQ*NH*HD];    // concat heads [b,s,h*d] fp16

#define SW128(off) ((off) ^ (((off) >> 3) & 0x70))

__device__ __forceinline__ uint32_t smem_u32(const void* p) {
    uint32_t a;
    asm("{ .reg .u64 t; cvta.to.shared.u64 t, %1; cvt.u32.u64 %0, t; }" : "=r"(a) : "l"(p));
    return a;
}
__device__ __forceinline__ void mma16816(float c[4], const uint32_t a[4], const uint32_t b[2]) {
    asm volatile("mma.sync.aligned.m16n8k16.row.col.f32.f16.f16.f32 "
        "{%0,%1,%2,%3}, {%4,%5,%6,%7}, {%8,%9}, {%0,%1,%2,%3};"
        : "+f"(c[0]), "+f"(c[1]), "+f"(c[2]), "+f"(c[3])
        : "r"(a[0]), "r"(a[1]), "r"(a[2]), "r"(a[3]), "r"(b[0]), "r"(b[1]));
}
// fp16-accumulated MMA: c-frag (2 regs) doubles as the P a-frag after in-place exp
__device__ __forceinline__ void mma16816_f16(uint32_t c[2], const uint32_t a[4], const uint32_t b[2]) {
    asm volatile("mma.sync.aligned.m16n8k16.row.col.f16.f16.f16.f16 "
        "{%0,%1}, {%2,%3,%4,%5}, {%6,%7}, {%0,%1};"
        : "+r"(c[0]), "+r"(c[1])
        : "r"(a[0]), "r"(a[1]), "r"(a[2]), "r"(a[3]), "r"(b[0]), "r"(b[1]));
}
__device__ __forceinline__ void ldsm_x4(uint32_t d[4], uint32_t addr) {
    asm volatile("ldmatrix.sync.aligned.m8n8.x4.shared.b16 {%0,%1,%2,%3}, [%4];"
        : "=r"(d[0]), "=r"(d[1]), "=r"(d[2]), "=r"(d[3]) : "r"(addr));
}
__device__ __forceinline__ void cp16(uint32_t sdst, const void* gsrc) {
    asm volatile("cp.async.cg.shared.global [%0], [%1], 16;" :: "r"(sdst), "l"(gsrc));
}
#define CP_COMMIT() asm volatile("cp.async.commit_group;" ::: "memory")
#define CP_WAIT(n)  asm volatile("cp.async.wait_group %0;" :: "n"(n) : "memory")

// ---------------- kernel 1a: convert x to fp16 + pack bias ----------------
__global__ void prep_kernel(const float* __restrict__ x,
                            const float* __restrict__ bk,
                            const float* __restrict__ bv,
                            const float* __restrict__ bq)
{
    int idx = blockIdx.x * blockDim.x + threadIdx.x;

    if (idx < MTOT*WRD/8) {
        float4 a = *(const float4*)(x + idx*8);
        float4 b = *(const float4*)(x + idx*8 + 4);
        __half2 h[4] = { __floats2half2_rn(a.x, a.y), __floats2half2_rn(a.z, a.w),
                         __floats2half2_rn(b.x, b.y), __floats2half2_rn(b.z, b.w) };
        *(uint2*)(g_xh + idx*8)     = *(uint2*)&h[0];
        *(uint2*)(g_xh + idx*8 + 4) = *(uint2*)&h[2];
    }

    if (idx < NQKV) {
        float v;
        if (idx < 64)       v = bk[idx];
        else if (idx < 128) v = bv[idx-64];
        else                v = bq[idx-128];
        g_ball[idx] = v;
    }
}

// ---------------- kernel 1b: coalesced smem-tile weight transposes ----------------
__global__ void wtrans_kernel(const float* __restrict__ Wk, const float* __restrict__ Wv,
                              const float* __restrict__ Wq, const float* __restrict__ Wp)
{
    __shared__ float t[32][33];
    const int slab = blockIdx.z;
    const int k0 = blockIdx.x * 32, n0 = blockIdx.y * 32;
    const float* src;
    __half* dst;
    if (slab == 0)      src = Wk;
    else if (slab == 1) src = Wv;
    else if (slab < 10) src = Wq + (size_t)(slab-2)*WRD*HD;
    else                src = Wp;
    dst = (slab < 10) ? (g_WhT + (size_t)slab*64*WRD) : g_WpT;

    const int tx = threadIdx.x, ty = threadIdx.y;   // (32, 8)
    #pragma unroll
    for (int r = 0; r < 4; r++)
        t[ty + r*8][tx] = src[(size_t)(k0 + ty + r*8)*HD + n0 + tx];
    __syncthreads();
    #pragma unroll
    for (int r = 0; r < 4; r++) {
        int n = ty + r*8;
        dst[(size_t)(n0 + n)*WRD + k0 + tx] = __float2half_rn(t[tx][n]);
    }
}

// ---------------- kernel 2: QKV projection, cp.async double-buffered ----------------
// grid (64, 10), 256 thr (8 warps x 16 m-rows). Tile 128m x 64n, K-step 64.
__global__ __launch_bounds__(256) void qkv_mma_kernel()
{
    __shared__ __align__(128) char sA[2][128*128];   // 2 x 16KB
    __shared__ __align__(128) char sB[2][64*128];    // 2 x  8KB

    const int tid = threadIdx.x;
    const int wid = tid >> 5, lane = tid & 31;
    const int m0 = blockIdx.x * 128, n0 = blockIdx.y * 64;

    auto load_tiles = [&](int buf, int k0) {
        #pragma unroll
        for (int r = 0; r < 4; r++) {
            int i = tid + r*256;
            int row = i >> 3, c8 = (i & 7) * 8;
            cp16(smem_u32(sA[buf]) + SW128((uint32_t)(row*128 + c8*2)),
                 g_xh + (size_t)(m0 + row)*WRD + k0 + c8);
        }
        #pragma unroll
        for (int r = 0; r < 2; r++) {
            int i = tid + r*256;
            int row = i >> 3, c8 = (i & 7) * 8;
            cp16(smem_u32(sB[buf]) + SW128((uint32_t)(row*128 + c8*2)),
                 g_WhT + (size_t)(n0 + row)*WRD + k0 + c8);
        }
    };

    float acc[8][4] = {};

    load_tiles(0, 0); CP_COMMIT();

    for (int ki = 0; ki < 8; ki++) {
        if (ki < 7) { load_tiles((ki+1)&1, (ki+1)*64); CP_COMMIT(); CP_WAIT(1); }
        else CP_WAIT(0);
        __syncthreads();

        const uint32_t ab = smem_u32(sA[ki&1]), bb = smem_u32(sB[ki&1]);
        #pragma unroll
        for (int kk = 0; kk < 4; kk++) {
            uint32_t afr[4];
            {
                int row = wid*16 + (lane & 7) + ((lane >> 3) & 1) * 8;
                uint32_t col = (uint32_t)(kk*32 + ((lane >> 4) ? 16 : 0));
                ldsm_x4(afr, ab + SW128((uint32_t)row*128 + col));
            }
            uint32_t colb = (uint32_t)(kk*32 + ((lane & 8) ? 16 : 0));
            uint32_t rwb  = (uint32_t)(((lane & 16) ? 8 : 0) + (lane & 7));
            #pragma unroll
            for (int j2 = 0; j2 < 4; j2++) {
                uint32_t bfr[4];
                ldsm_x4(bfr, bb + SW128((j2*16 + rwb)*128 + colb));
                mma16816(acc[2*j2],   afr, bfr);
                mma16816(acc[2*j2+1], afr, bfr + 2);
            }
        }
        __syncthreads();
    }

    // ---- epilogue: bias + scatter to K / V^T / Q ----
    int r = wid*16 + (lane >> 2);
    #pragma unroll
    for (int j = 0; j < 8; j++) {
        #pragma unroll
        for (int e = 0; e < 2; e++) {
            int n = n0 + j*8 + (lane & 3)*2 + e;
            float bias = g_ball[n];
            #pragma unroll
            for (int rr = 0; rr < 2; rr++) {
                int m = m0 + r + rr*8;
                float v = acc[j][rr*2 + e] + bias;
                int b = m >> 12, s = m & 4095;
                if (n < 64) {
                    g_Kh[((size_t)b*SEQ + s)*HD + n] = __float2half_rn(v);
                } else if (n < 128) {
                    g_Vth[((size_t)b*HD + (n-64))*SEQ + s] = __float2half_rn(v);
                } else {
                    int nn = n - 128; int h = nn >> 6, d = nn & 63;
                    g_Qh[(((size_t)b*NH + h)*SEQ + s)*HD + d] = __float2half_rn(v * QSCALE);
                }
            }
        }
    }
}

// ---------------- kernel 3: mma.sync flash attention, pipelined + MUFU interleave ----------------
// grid (SEQ/128, NH, BATCH), 128 threads = 4 warps x 32 q-rows, 2 CTAs/SM.
// 3-deep K/V smem ring (Q staging overlays slot 2). Per step kt: S(kt+1) raw, then
// PV(kt) with exp(kt+1) interleaved per-tt into the PV MMA stream (MUFU never clumps).
__global__ __launch_bounds__(128, 2) void attn_mma_kernel()
{
    __shared__ __align__(128) char smemAll[3*16384];   // 48KB ring; slot2 doubles as Q staging

    const int tid  = threadIdx.x;
    const int wid  = tid >> 5, lane = tid & 31;
    const int b = blockIdx.z, hh = blockIdx.y, q0 = blockIdx.x * 128;

    const __half* Qp = g_Qh + ((size_t)(b*NH + hh)*SEQ + q0) * HD;
    const __half* Kp = g_Kh  + (size_t)b*SEQ*HD;
    const __half* Vp = g_Vth + (size_t)b*HD*SEQ;

    auto kbuf = [&](int r) -> char* { return smemAll + r*16384; };
    auto vbuf = [&](int r) -> char* { return smemAll + r*16384 + 8192; };
    char* sQ = smemAll + 2*16384;

    auto load_kv = [&](int bufr, int kt) {
        char* kb = kbuf(bufr); char* vb = vbuf(bufr);
        #pragma unroll
        for (int r = 0; r < 4; r++) {
            int i = tid + r*128;
            int row = i >> 3, c8 = (i & 7) * 8;
            uint32_t off = SW128((uint32_t)(row*128 + c8*2));
            cp16(smem_u32(kb) + off, Kp + (size_t)(kt*64 + row)*HD + c8);
            cp16(smem_u32(vb) + off, Vp + (size_t)row*SEQ + kt*64 + c8);
        }
    };

    load_kv(0, 0); CP_COMMIT();
    load_kv(1, 1); CP_COMMIT();

    // ---- Q tile -> smem slot2 -> register a-frags ----
    #pragma unroll
    for (int r = 0; r < 8; r++) {
        int i = tid + r*128;
        int row = i >> 3, c8 = (i & 7) * 8;
        *(uint4*)(sQ + SW128((uint32_t)(row*128 + c8*2))) = *(const uint4*)(Qp + row*HD + c8);
    }
    __syncthreads();
    uint32_t qa[2][4][4];
    {
        const uint32_t qb = smem_u32(sQ);
        #pragma unroll
        for (int a = 0; a < 2; a++) {
            int row = wid*32 + a*16 + (lane & 7) + ((lane >> 3) & 1) * 8;
            #pragma unroll
            for (int kk = 0; kk < 4; kk++) {
                uint32_t col = (uint32_t)(kk*32 + ((lane >> 4) ? 16 : 0));
                ldsm_x4(qa[a][kk], qb + SW128((uint32_t)row*128 + col));
            }
        }
    }

    float oc[2][8][4] = {};
    float lsacc[2][4] = {};
    const uint32_t ones_frag[2] = { 0x3C003C00u, 0x3C003C00u };  // fp16 1.0 x4
    const uint32_t colb = (uint32_t)((lane & 8) ? 16 : 0);
    const uint32_t rwb  = (uint32_t)(((lane & 16) ? 8 : 0) + (lane & 7));

    uint32_t scfA[2][8][2], scfB[2][8][2];

#define S_COMPUTE(SCF, KBASE) do { \
    const uint32_t _kb = (KBASE); \
    _Pragma("unroll") for (int a = 0; a < 2; a++) \
      _Pragma("unroll") for (int j = 0; j < 8; j++) { SCF[a][j][0] = 0u; SCF[a][j][1] = 0u; } \
    _Pragma("unroll") for (int kk = 0; kk < 4; kk++) { \
        uint32_t cc = (uint32_t)(kk*32) + colb; \
        _Pragma("unroll") for (int j2 = 0; j2 < 4; j2++) { \
            uint32_t bfr[4]; \
            ldsm_x4(bfr, _kb + SW128((j2*16 + rwb)*128 + cc)); \
            _Pragma("unroll") for (int a = 0; a < 2; a++) { \
                mma16816_f16(SCF[a][2*j2],   qa[a][kk], bfr); \
                mma16816_f16(SCF[a][2*j2+1], qa[a][kk], bfr + 2); \
            } } } } while (0)

// PV of CUR with exp of NXT interleaved per tt-group (8 MUFU ops per group,
// evenly spread across the PV MMA stream). DOEXP=false -> plain PV.
#define PV_EXP(CUR, NXT, VBASE, DOEXP) do { \
    const uint32_t _vb = (VBASE); \
    _Pragma("unroll") for (int tt = 0; tt < 4; tt++) { \
        uint32_t cc = (uint32_t)(tt*32) + colb; \
        uint32_t pa[2][4]; \
        _Pragma("unroll") for (int a = 0; a < 2; a++) { \
            pa[a][0] = CUR[a][2*tt][0];   pa[a][1] = CUR[a][2*tt][1]; \
            pa[a][2] = CUR[a][2*tt+1][0]; pa[a][3] = CUR[a][2*tt+1][1]; } \
        _Pragma("unroll") for (int jv = 0; jv < 4; jv++) { \
            uint32_t bfr[4]; \
            ldsm_x4(bfr, _vb + SW128((jv*16 + rwb)*128 + cc)); \
            _Pragma("unroll") for (int a = 0; a < 2; a++) { \
                mma16816(oc[a][2*jv],   pa[a], bfr); \
                mma16816(oc[a][2*jv+1], pa[a], bfr + 2); } } \
        _Pragma("unroll") for (int a = 0; a < 2; a++) \
            mma16816(lsacc[a], pa[a], ones_frag); \
        if (DOEXP) { \
            _Pragma("unroll") for (int a = 0; a < 2; a++) \
              _Pragma("unroll") for (int jj = 0; jj < 2; jj++) { \
                int _j = 2*tt + jj; \
                __half2 e0 = h2exp2(*(__half2*)&NXT[a][_j][0]); \
                __half2 e1 = h2exp2(*(__half2*)&NXT[a][_j][1]); \
                NXT[a][_j][0] = *(uint32_t*)&e0; NXT[a][_j][1] = *(uint32_t*)&e1; } \
        } } } while (0)

#define STEP(CUR, NXT, KT, HASNEXT) do { \
    CP_WAIT(0); \
    __syncthreads(); \
    if ((HASNEXT) && (KT) + 2 < NKT) { load_kv(((KT)+2)%3, (KT)+2); CP_COMMIT(); } \
    if (HASNEXT) { S_COMPUTE(NXT, smem_u32(kbuf(((KT)+1)%3))); } \
    PV_EXP(CUR, NXT, smem_u32(vbuf((KT)%3)), (HASNEXT)); \
} while (0)

    // ---- prologue: S(0) + exp(0) into scfA (K in slot0) ----
    CP_WAIT(1);
    __syncthreads();
    S_COMPUTE(scfA, smem_u32(kbuf(0)));
    #pragma unroll
    for (int a = 0; a < 2; a++)
        #pragma unroll
        for (int j = 0; j < 8; j++) {
            __half2 e0 = h2exp2(*(__half2*)&scfA[a][j][0]);
            __half2 e1 = h2exp2(*(__half2*)&scfA[a][j][1]);
            scfA[a][j][0] = *(uint32_t*)&e0; scfA[a][j][1] = *(uint32_t*)&e1;
        }

    // ---- pipelined mainloop ----
    for (int kt = 0; kt < NKT - 2; kt += 2) {
        STEP(scfA, scfB, kt,   true);
        STEP(scfB, scfA, kt+1, true);
    }
    STEP(scfA, scfB, NKT-2, true);
    STEP(scfB, scfA, NKT-1, false);

    // ---- write O (fp16 concat-head layout); lsum complete per lane ----
    int c0 = (lane & 3) * 2;
    #pragma unroll
    for (int a = 0; a < 2; a++) {
        float inv0 = 1.0f / lsacc[a][0], inv1 = 1.0f / lsacc[a][2];
        int r = wid*32 + a*16 + (lane >> 2);
        __half* Z0 = g_Zch + ((size_t)(b*SEQ) + q0 + r    )*(NH*HD) + hh*HD;
        __half* Z1 = g_Zch + ((size_t)(b*SEQ) + q0 + r + 8)*(NH*HD) + hh*HD;
        #pragma unroll
        for (int j = 0; j < 8; j++) {
            int d = j*8 + c0;
            *(__half2*)(Z0 + d) = __floats2half2_rn(oc[a][j][0]*inv0, oc[a][j][1]*inv0);
            *(__half2*)(Z1 + d) = __floats2half2_rn(oc[a][j][2]*inv1, oc[a][j][3]*inv1);
        }
    }
}

// ---------------- kernel 4: output projection, cp.async double-buffered ----------------
// grid (128), 128 thr (4 warps x 16 m-rows). Tile 64m x 64n, K-step 64.
__global__ __launch_bounds__(128) void oproj_mma_kernel(const float* __restrict__ bp,
                                                        float* __restrict__ out)
{
    __shared__ __align__(128) char sA[2][64*128];    // 2 x 8KB
    __shared__ __align__(128) char sB[2][64*128];    // 2 x 8KB

    const int tid = threadIdx.x;
    const int wid = tid >> 5, lane = tid & 31;
    const int m0 = blockIdx.x * 64;

    auto load_tiles = [&](int buf, int k0) {
        #pragma unroll
        for (int r = 0; r < 4; r++) {
            int i = tid + r*128;
            int row = i >> 3, c8 = (i & 7) * 8;
            uint32_t off = SW128((uint32_t)(row*128 + c8*2));
            cp16(smem_u32(sA[buf]) + off, g_Zch + (size_t)(m0 + row)*WRD + k0 + c8);
            cp16(smem_u32(sB[buf]) + off, g_WpT + (size_t)row*WRD + k0 + c8);
        }
    };

    float acc[8][4] = {};

    load_tiles(0, 0); CP_COMMIT();

    for (int ki = 0; ki < 8; ki++) {
        if (ki < 7) { load_tiles((ki+1)&1, (ki+1)*64); CP_COMMIT(); CP_WAIT(1); }
        else CP_WAIT(0);
        __syncthreads();

        const uint32_t ab = smem_u32(sA[ki&1]), bb = smem_u32(sB[ki&1]);
        #pragma unroll
        for (int kk = 0; kk < 4; kk++) {
            uint32_t afr[4];
            {
                int row = wid*16 + (lane & 7) + ((lane >> 3) & 1) * 8;
                uint32_t col = (uint32_t)(kk*32 + ((lane >> 4) ? 16 : 0));
                ldsm_x4(afr, ab + SW128((uint32_t)row*128 + col));
            }
            uint32_t colb = (uint32_t)(kk*32 + ((lane & 8) ? 16 : 0));
            uint32_t rwb  = (uint32_t)(((lane & 16) ? 8 : 0) + (lane & 7));
            #pragma unroll
            for (int j2 = 0; j2 < 4; j2++) {
                uint32_t bfr[4];
                ldsm_x4(bfr, bb + SW128((j2*16 + rwb)*128 + colb));
                mma16816(acc[2*j2],   afr, bfr);
                mma16816(acc[2*j2+1], afr, bfr + 2);
            }
        }
        __syncthreads();
    }

    int r  = wid*16 + (lane >> 2);
    int c0 = (lane & 3) * 2;
    float* O0 = out + (size_t)(m0 + r    )*HD;
    float* O1 = out + (size_t)(m0 + r + 8)*HD;
    #pragma unroll
    for (int j = 0; j < 8; j++) {
        int n = j*8 + c0;
        float b0 = bp[n], b1 = bp[n+1];
        *(float2*)(O0 + n) = make_float2(acc[j][0] + b0, acc[j][1] + b1);
        *(float2*)(O1 + n) = make_float2(acc[j][2] + b0, acc[j][3] + b1);
    }
}

// ---------------- launch ----------------
extern "C" void kernel_launch(void* const* d_in, const int* in_sizes, int n_in,
                              void* d_out, int out_size)
{
    const float* x  = (const float*)d_in[0];
    const float* Wq = (const float*)d_in[1];
    const float* bq = (const float*)d_in[2];
    const float* Wk = (const float*)d_in[3];
    const float* bk = (const float*)d_in[4];
    const float* Wv = (const float*)d_in[5];
    const float* bv = (const float*)d_in[6];
    const float* Wp = (const float*)d_in[7];
    const float* bp = (const float*)d_in[8];
    float* out = (float*)d_out;

    prep_kernel<<<(MTOT*WRD/8 + 255)/256, 256>>>(x, bk, bv, bq);
    wtrans_kernel<<<dim3(16, 2, 11), dim3(32, 8)>>>(Wk, Wv, Wq, Wp);

    qkv_mma_kernel<<<dim3(MTOT/128, NQKV/64), 256>>>();

    attn_mma_kernel<<<dim3(SEQ/128, NH, BATCH), 128>>>();

    oproj_mma_kernel<<<dim3(MTOT/64), 128>>>(bp, out);
}

// round 13
// speedup vs baseline: 1.0067x; 1.0067x over previous
#include <cuda_runtime.h>
#include <cuda_fp16.h>
#include <math.h>
#include <cstdint>

#define BATCH 2
#define NH    8
#define SEQ   4096
#define HD    64
#define WRD   512
#define MTOT  (BATCH*SEQ)     // 8192
#define NQKV  640             // 64 (K) + 64 (V) + 8*64 (Q)
#define NKT2  (SEQ/128)       // 32 key tiles of 128

// Q pre-scale: (1/sqrt(64)) * log2(e)  -> scores in log2 domain, exp2 for softmax
#define QSCALE 0.18033688011112042f

// ---------------- scratch (device globals; no allocation allowed) ----------------
__device__ __half g_xh[MTOT*WRD];            // x fp16 [8192,512]
__device__ __half g_WhT[NQKV*WRD];           // packed QKV weight, transposed [n][k] fp16
__device__ __half g_WpT[HD*WRD];             // Wp transposed [n][k] fp16
__device__ float  g_ball[NQKV];              // packed QKV bias fp32
__device__ __half g_Kh[BATCH*SEQ*HD];        // K  [b,t,d] fp16
__device__ __half g_Vth[BATCH*HD*SEQ];       // V^T [b,d,t] fp16
__device__ __half g_Qh[BATCH*NH*SEQ*HD];     // Q  [b,h,s,d] fp16 (pre-scaled)
__device__ __half g_Zch[BATCH*SEQ*NH*HD];    // concat heads [b,s,h*d] fp16

#define SW128(off) ((off) ^ (((off) >> 3) & 0x70))

__device__ __forceinline__ uint32_t smem_u32(const void* p) {
    uint32_t a;
    asm("{ .reg .u64 t; cvta.to.shared.u64 t, %1; cvt.u32.u64 %0, t; }" : "=r"(a) : "l"(p));
    return a;
}
__device__ __forceinline__ void mma16816(float c[4], const uint32_t a[4], const uint32_t b[2]) {
    asm volatile("mma.sync.aligned.m16n8k16.row.col.f32.f16.f16.f32 "
        "{%0,%1,%2,%3}, {%4,%5,%6,%7}, {%8,%9}, {%0,%1,%2,%3};"
        : "+f"(c[0]), "+f"(c[1]), "+f"(c[2]), "+f"(c[3])
        : "r"(a[0]), "r"(a[1]), "r"(a[2]), "r"(a[3]), "r"(b[0]), "r"(b[1]));
}
// fp16-accumulated MMA: c-frag (2 regs) doubles as the P a-frag after in-place exp
__device__ __forceinline__ void mma16816_f16(uint32_t c[2], const uint32_t a[4], const uint32_t b[2]) {
    asm volatile("mma.sync.aligned.m16n8k16.row.col.f16.f16.f16.f16 "
        "{%0,%1}, {%2,%3,%4,%5}, {%6,%7}, {%0,%1};"
        : "+r"(c[0]), "+r"(c[1])
        : "r"(a[0]), "r"(a[1]), "r"(a[2]), "r"(a[3]), "r"(b[0]), "r"(b[1]));
}
__device__ __forceinline__ void ldsm_x4(uint32_t d[4], uint32_t addr) {
    asm volatile("ldmatrix.sync.aligned.m8n8.x4.shared.b16 {%0,%1,%2,%3}, [%4];"
        : "=r"(d[0]), "=r"(d[1]), "=r"(d[2]), "=r"(d[3]) : "r"(addr));
}
__device__ __forceinline__ void cp16(uint32_t sdst, const void* gsrc) {
    asm volatile("cp.async.cg.shared.global [%0], [%1], 16;" :: "r"(sdst), "l"(gsrc));
}
#define CP_COMMIT() asm volatile("cp.async.commit_group;" ::: "memory")
#define CP_WAIT(n)  asm volatile("cp.async.wait_group %0;" :: "n"(n) : "memory")

// ---------------- kernel 1a: convert x to fp16 + pack bias ----------------
__global__ void prep_kernel(const float* __restrict__ x,
                            const float* __restrict__ bk,
                            const float* __restrict__ bv,
                            const float* __restrict__ bq)
{
    int idx = blockIdx.x * blockDim.x + threadIdx.x;

    if (idx < MTOT*WRD/8) {
        float4 a = *(const float4*)(x + idx*8);
        float4 b = *(const float4*)(x + idx*8 + 4);
        __half2 h[4] = { __floats2half2_rn(a.x, a.y), __floats2half2_rn(a.z, a.w),
                         __floats2half2_rn(b.x, b.y), __floats2half2_rn(b.z, b.w) };
        *(uint2*)(g_xh + idx*8)     = *(uint2*)&h[0];
        *(uint2*)(g_xh + idx*8 + 4) = *(uint2*)&h[2];
    }

    if (idx < NQKV) {
        float v;
        if (idx < 64)       v = bk[idx];
        else if (idx < 128) v = bv[idx-64];
        else                v = bq[idx-128];
        g_ball[idx] = v;
    }
}

// ---------------- kernel 1b: coalesced smem-tile weight transposes ----------------
__global__ void wtrans_kernel(const float* __restrict__ Wk, const float* __restrict__ Wv,
                              const float* __restrict__ Wq, const float* __restrict__ Wp)
{
    __shared__ float t[32][33];
    const int slab = blockIdx.z;
    const int k0 = blockIdx.x * 32, n0 = blockIdx.y * 32;
    const float* src;
    __half* dst;
    if (slab == 0)      src = Wk;
    else if (slab == 1) src = Wv;
    else if (slab < 10) src = Wq + (size_t)(slab-2)*WRD*HD;
    else                src = Wp;
    dst = (slab < 10) ? (g_WhT + (size_t)slab*64*WRD) : g_WpT;

    const int tx = threadIdx.x, ty = threadIdx.y;   // (32, 8)
    #pragma unroll
    for (int r = 0; r < 4; r++)
        t[ty + r*8][tx] = src[(size_t)(k0 + ty + r*8)*HD + n0 + tx];
    __syncthreads();
    #pragma unroll
    for (int r = 0; r < 4; r++) {
        int n = ty + r*8;
        dst[(size_t)(n0 + n)*WRD + k0 + tx] = __float2half_rn(t[tx][n]);
    }
}

// ---------------- kernel 2: QKV projection, cp.async double-buffered ----------------
// grid (64, 10), 256 thr (8 warps x 16 m-rows). Tile 128m x 64n, K-step 64.
__global__ __launch_bounds__(256) void qkv_mma_kernel()
{
    __shared__ __align__(128) char sA[2][128*128];   // 2 x 16KB
    __shared__ __align__(128) char sB[2][64*128];    // 2 x  8KB

    const int tid = threadIdx.x;
    const int wid = tid >> 5, lane = tid & 31;
    const int m0 = blockIdx.x * 128, n0 = blockIdx.y * 64;

    auto load_tiles = [&](int buf, int k0) {
        #pragma unroll
        for (int r = 0; r < 4; r++) {
            int i = tid + r*256;
            int row = i >> 3, c8 = (i & 7) * 8;
            cp16(smem_u32(sA[buf]) + SW128((uint32_t)(row*128 + c8*2)),
                 g_xh + (size_t)(m0 + row)*WRD + k0 + c8);
        }
        #pragma unroll
        for (int r = 0; r < 2; r++) {
            int i = tid + r*256;
            int row = i >> 3, c8 = (i & 7) * 8;
            cp16(smem_u32(sB[buf]) + SW128((uint32_t)(row*128 + c8*2)),
                 g_WhT + (size_t)(n0 + row)*WRD + k0 + c8);
        }
    };

    float acc[8][4] = {};

    load_tiles(0, 0); CP_COMMIT();

    for (int ki = 0; ki < 8; ki++) {
        if (ki < 7) { load_tiles((ki+1)&1, (ki+1)*64); CP_COMMIT(); CP_WAIT(1); }
        else CP_WAIT(0);
        __syncthreads();

        const uint32_t ab = smem_u32(sA[ki&1]), bb = smem_u32(sB[ki&1]);
        #pragma unroll
        for (int kk = 0; kk < 4; kk++) {
            uint32_t afr[4];
            {
                int row = wid*16 + (lane & 7) + ((lane >> 3) & 1) * 8;
                uint32_t col = (uint32_t)(kk*32 + ((lane >> 4) ? 16 : 0));
                ldsm_x4(afr, ab + SW128((uint32_t)row*128 + col));
            }
            uint32_t colb = (uint32_t)(kk*32 + ((lane & 8) ? 16 : 0));
            uint32_t rwb  = (uint32_t)(((lane & 16) ? 8 : 0) + (lane & 7));
            #pragma unroll
            for (int j2 = 0; j2 < 4; j2++) {
                uint32_t bfr[4];
                ldsm_x4(bfr, bb + SW128((j2*16 + rwb)*128 + colb));
                mma16816(acc[2*j2],   afr, bfr);
                mma16816(acc[2*j2+1], afr, bfr + 2);
            }
        }
        __syncthreads();
    }

    // ---- epilogue: bias + scatter to K / V^T / Q ----
    int r = wid*16 + (lane >> 2);
    #pragma unroll
    for (int j = 0; j < 8; j++) {
        #pragma unroll
        for (int e = 0; e < 2; e++) {
            int n = n0 + j*8 + (lane & 3)*2 + e;
            float bias = g_ball[n];
            #pragma unroll
            for (int rr = 0; rr < 2; rr++) {
                int m = m0 + r + rr*8;
                float v = acc[j][rr*2 + e] + bias;
                int b = m >> 12, s = m & 4095;
                if (n < 64) {
                    g_Kh[((size_t)b*SEQ + s)*HD + n] = __float2half_rn(v);
                } else if (n < 128) {
                    g_Vth[((size_t)b*HD + (n-64))*SEQ + s] = __float2half_rn(v);
                } else {
                    int nn = n - 128; int h = nn >> 6, d = nn & 63;
                    g_Qh[(((size_t)b*NH + h)*SEQ + s)*HD + d] = __float2half_rn(v * QSCALE);
                }
            }
        }
    }
}

// ---------------- kernel 3: mma.sync flash attention, 128-key steps, 3-slot dynamic ring ----------------
// grid (SEQ/128, NH, BATCH), 128 threads = 4 warps x 32 q-rows, 2 CTAs/SM.
// Slot = K [128t][64d] 16KB + V^T as two [64d][64t] sub-tiles 16KB. 3 slots = 96KB dynamic.
// 32 steps (half the barriers). Per step: monolithic S (64 indep f16 MMAs), then per-tt
// [exp group tt -> PV group tt] so MUFU interleaves with the PV MMA stream.
__global__ __launch_bounds__(128, 2) void attn_mma_kernel()
{
    extern __shared__ __align__(128) char smemAll[];   // 3 x 32768; slot2 doubles as Q staging

    const int tid  = threadIdx.x;
    const int wid  = tid >> 5, lane = tid & 31;
    const int b = blockIdx.z, hh = blockIdx.y, q0 = blockIdx.x * 128;

    const __half* Qp = g_Qh + ((size_t)(b*NH + hh)*SEQ + q0) * HD;
    const __half* Kp = g_Kh  + (size_t)b*SEQ*HD;
    const __half* Vp = g_Vth + (size_t)b*HD*SEQ;

    auto kbuf = [&](int r) -> char* { return smemAll + r*32768; };
    auto vbuf = [&](int r) -> char* { return smemAll + r*32768 + 16384; };
    char* sQ = smemAll + 2*32768;

    auto load_kv = [&](int slot, int kt) {
        char* kb = kbuf(slot); char* vb = vbuf(slot);
        // K: 128 rows x 64 halves = 1024 chunks (8/thread)
        #pragma unroll
        for (int r = 0; r < 8; r++) {
            int i = tid + r*128;
            int row = i >> 3, c8 = (i & 7) * 8;
            cp16(smem_u32(kb) + SW128((uint32_t)(row*128 + c8*2)),
                 Kp + (size_t)(kt*128 + row)*HD + c8);
        }
        // V^T: 64 d-rows x 128 t, as 2 sub-tiles of [64][64] (8/thread)
        #pragma unroll
        for (int r = 0; r < 8; r++) {
            int i = tid + r*128;
            int d = i >> 4, t16 = (i & 15) * 8;
            int sub = t16 >> 6, tloc = t16 & 63;
            cp16(smem_u32(vb) + (uint32_t)(sub*8192) + SW128((uint32_t)(d*128 + tloc*2)),
                 Vp + (size_t)d*SEQ + kt*128 + t16);
        }
    };

    load_kv(0, 0); CP_COMMIT();
    load_kv(1, 1); CP_COMMIT();

    // ---- Q tile -> smem slot2 -> register a-frags ----
    #pragma unroll
    for (int r = 0; r < 8; r++) {
        int i = tid + r*128;
        int row = i >> 3, c8 = (i & 7) * 8;
        *(uint4*)(sQ + SW128((uint32_t)(row*128 + c8*2))) = *(const uint4*)(Qp + row*HD + c8);
    }
    __syncthreads();
    uint32_t qa[2][4][4];
    {
        const uint32_t qb = smem_u32(sQ);
        #pragma unroll
        for (int a = 0; a < 2; a++) {
            int row = wid*32 + a*16 + (lane & 7) + ((lane >> 3) & 1) * 8;
            #pragma unroll
            for (int kk = 0; kk < 4; kk++) {
                uint32_t col = (uint32_t)(kk*32 + ((lane >> 4) ? 16 : 0));
                ldsm_x4(qa[a][kk], qb + SW128((uint32_t)row*128 + col));
            }
        }
    }

    float oc[2][8][4] = {};
    float lsacc[2][4] = {};
    const uint32_t ones_frag[2] = { 0x3C003C00u, 0x3C003C00u };  // fp16 1.0 x4
    const uint32_t colb = (uint32_t)((lane & 8) ? 16 : 0);
    const uint32_t rwb  = (uint32_t)(((lane & 16) ? 8 : 0) + (lane & 7));

    for (int kt = 0; kt < NKT2; kt++) {
        CP_WAIT(0);
        __syncthreads();   // slot kt%3 data visible; all warps done with slot (kt+2)%3
        if (kt + 2 < NKT2) { load_kv((kt+2)%3, kt+2); CP_COMMIT(); }

        const uint32_t kb_ = smem_u32(kbuf(kt%3));
        const uint32_t vb_ = smem_u32(vbuf(kt%3));

        // ---- S = Q @ K^T over 128 keys, fp16 accumulate (16 n-tiles) ----
        uint32_t scf[2][16][2];
        #pragma unroll
        for (int a = 0; a < 2; a++)
            #pragma unroll
            for (int j = 0; j < 16; j++) { scf[a][j][0] = 0u; scf[a][j][1] = 0u; }
        #pragma unroll
        for (int kk = 0; kk < 4; kk++) {
            uint32_t cc = (uint32_t)(kk*32) + colb;
            #pragma unroll
            for (int j2 = 0; j2 < 8; j2++) {
                uint32_t bfr[4];
                ldsm_x4(bfr, kb_ + SW128((uint32_t)(j2*16 + rwb)*128 + cc));
                #pragma unroll
                for (int a = 0; a < 2; a++) {
                    mma16816_f16(scf[a][2*j2],   qa[a][kk], bfr);
                    mma16816_f16(scf[a][2*j2+1], qa[a][kk], bfr + 2);
                }
            }
        }

        // ---- per tt-group: exp (8 MUFU) then PV (9 MMAs x2a) — scheduler interleaves ----
        #pragma unroll
        for (int tt = 0; tt < 8; tt++) {
            uint32_t pa[2][4];
            #pragma unroll
            for (int a = 0; a < 2; a++) {
                __half2 e0 = h2exp2(*(__half2*)&scf[a][2*tt][0]);
                __half2 e1 = h2exp2(*(__half2*)&scf[a][2*tt][1]);
                __half2 e2 = h2exp2(*(__half2*)&scf[a][2*tt+1][0]);
                __half2 e3 = h2exp2(*(__half2*)&scf[a][2*tt+1][1]);
                pa[a][0] = *(uint32_t*)&e0;
                pa[a][1] = *(uint32_t*)&e1;
                pa[a][2] = *(uint32_t*)&e2;
                pa[a][3] = *(uint32_t*)&e3;
            }
            uint32_t vblk = vb_ + (uint32_t)((tt >> 2)*8192);
            uint32_t cc = (uint32_t)((tt & 3)*32) + colb;
            #pragma unroll
            for (int jv = 0; jv < 4; jv++) {
                uint32_t bfr[4];
                ldsm_x4(bfr, vblk + SW128((uint32_t)(jv*16 + rwb)*128 + cc));
                #pragma unroll
                for (int a = 0; a < 2; a++) {
                    mma16816(oc[a][2*jv],   pa[a], bfr);
                    mma16816(oc[a][2*jv+1], pa[a], bfr + 2);
                }
            }
            #pragma unroll
            for (int a = 0; a < 2; a++)
                mma16816(lsacc[a], pa[a], ones_frag);
        }
    }

    // ---- write O (fp16 concat-head layout); lsum complete per lane ----
    int c0 = (lane & 3) * 2;
    #pragma unroll
    for (int a = 0; a < 2; a++) {
        float inv0 = 1.0f / lsacc[a][0], inv1 = 1.0f / lsacc[a][2];
        int r = wid*32 + a*16 + (lane >> 2);
        __half* Z0 = g_Zch + ((size_t)(b*SEQ) + q0 + r    )*(NH*HD) + hh*HD;
        __half* Z1 = g_Zch + ((size_t)(b*SEQ) + q0 + r + 8)*(NH*HD) + hh*HD;
        #pragma unroll
        for (int j = 0; j < 8; j++) {
            int d = j*8 + c0;
            *(__half2*)(Z0 + d) = __floats2half2_rn(oc[a][j][0]*inv0, oc[a][j][1]*inv0);
            *(__half2*)(Z1 + d) = __floats2half2_rn(oc[a][j][2]*inv1, oc[a][j][3]*inv1);
        }
    }
}

// ---------------- kernel 4: output projection, cp.async double-buffered ----------------
// grid (128), 128 thr (4 warps x 16 m-rows). Tile 64m x 64n, K-step 64.
__global__ __launch_bounds__(128) void oproj_mma_kernel(const float* __restrict__ bp,
                                                        float* __restrict__ out)
{
    __shared__ __align__(128) char sA[2][64*128];    // 2 x 8KB
    __shared__ __align__(128) char sB[2][64*128];    // 2 x 8KB

    const int tid = threadIdx.x;
    const int wid = tid >> 5, lane = tid & 31;
    const int m0 = blockIdx.x * 64;

    auto load_tiles = [&](int buf, int k0) {
        #pragma unroll
        for (int r = 0; r < 4; r++) {
            int i = tid + r*128;
            int row = i >> 3, c8 = (i & 7) * 8;
            uint32_t off = SW128((uint32_t)(row*128 + c8*2));
            cp16(smem_u32(sA[buf]) + off, g_Zch + (size_t)(m0 + row)*WRD + k0 + c8);
            cp16(smem_u32(sB[buf]) + off, g_WpT + (size_t)row*WRD + k0 + c8);
        }
    };

    float acc[8][4] = {};

    load_tiles(0, 0); CP_COMMIT();

    for (int ki = 0; ki < 8; ki++) {
        if (ki < 7) { load_tiles((ki+1)&1, (ki+1)*64); CP_COMMIT(); CP_WAIT(1); }
        else CP_WAIT(0);
        __syncthreads();

        const uint32_t ab = smem_u32(sA[ki&1]), bb = smem_u32(sB[ki&1]);
        #pragma unroll
        for (int kk = 0; kk < 4; kk++) {
            uint32_t afr[4];
            {
                int row = wid*16 + (lane & 7) + ((lane >> 3) & 1) * 8;
                uint32_t col = (uint32_t)(kk*32 + ((lane >> 4) ? 16 : 0));
                ldsm_x4(afr, ab + SW128((uint32_t)row*128 + col));
            }
            uint32_t colb = (uint32_t)(kk*32 + ((lane & 8) ? 16 : 0));
            uint32_t rwb  = (uint32_t)(((lane & 16) ? 8 : 0) + (lane & 7));
            #pragma unroll
            for (int j2 = 0; j2 < 4; j2++) {
                uint32_t bfr[4];
                ldsm_x4(bfr, bb + SW128((j2*16 + rwb)*128 + colb));
                mma16816(acc[2*j2],   afr, bfr);
                mma16816(acc[2*j2+1], afr, bfr + 2);
            }
        }
        __syncthreads();
    }

    int r  = wid*16 + (lane >> 2);
    int c0 = (lane & 3) * 2;
    float* O0 = out + (size_t)(m0 + r    )*HD;
    float* O1 = out + (size_t)(m0 + r + 8)*HD;
    #pragma unroll
    for (int j = 0; j < 8; j++) {
        int n = j*8 + c0;
        float b0 = bp[n], b1 = bp[n+1];
        *(float2*)(O0 + n) = make_float2(acc[j][0] + b0, acc[j][1] + b1);
        *(float2*)(O1 + n) = make_float2(acc[j][2] + b0, acc[j][3] + b1);
    }
}

// ---------------- launch ----------------
extern "C" void kernel_launch(void* const* d_in, const int* in_sizes, int n_in,
                              void* d_out, int out_size)
{
    const float* x  = (const float*)d_in[0];
    const float* Wq = (const float*)d_in[1];
    const float* bq = (const float*)d_in[2];
    const float* Wk = (const float*)d_in[3];
    const float* bk = (const float*)d_in[4];
    const float* Wv = (const float*)d_in[5];
    const float* bv = (const float*)d_in[6];
    const float* Wp = (const float*)d_in[7];
    const float* bp = (const float*)d_in[8];
    float* out = (float*)d_out;

    prep_kernel<<<(MTOT*WRD/8 + 255)/256, 256>>>(x, bk, bv, bq);
    wtrans_kernel<<<dim3(16, 2, 11), dim3(32, 8)>>>(Wk, Wv, Wq, Wp);

    qkv_mma_kernel<<<dim3(MTOT/128, NQKV/64), 256>>>();

    const int attn_smem = 3 * 32768;   // 96KB dynamic ring
    cudaFuncSetAttribute(attn_mma_kernel, cudaFuncAttributeMaxDynamicSharedMemorySize, attn_smem);
    attn_mma_kernel<<<dim3(SEQ/128, NH, BATCH), 128, attn_smem>>>();

    oproj_mma_kernel<<<dim3(MTOT/64), 128>>>(bp, out);
}

// round 14
// speedup vs baseline: 1.0187x; 1.0119x over previous
#include <cuda_runtime.h>
#include <cuda_fp16.h>
#include <math.h>
#include <cstdint>

#define BATCH 2
#define NH    8
#define SEQ   4096
#define HD    64
#define WRD   512
#define MTOT  (BATCH*SEQ)     // 8192
#define NQKV  640             // 64 (K) + 64 (V) + 8*64 (Q)
#define NKT2  (SEQ/128)       // 32 key tiles of 128

// Q pre-scale: (1/sqrt(64)) * log2(e)  -> scores in log2 domain, exp2 for softmax
#define QSCALE 0.18033688011112042f

// ---------------- scratch (device globals; no allocation allowed) ----------------
__device__ __half g_xh[MTOT*WRD];            // x fp16 [8192,512]
__device__ __half g_WhT[NQKV*WRD];           // packed QKV weight, transposed [n][k] fp16
__device__ __half g_WpT[HD*WRD];             // Wp transposed [n][k] fp16
__device__ float  g_ball[NQKV];              // packed QKV bias fp32
__device__ __half g_Kh[BATCH*SEQ*HD];        // K  [b,t,d] fp16
__device__ __half g_Vth[BATCH*HD*SEQ];       // V^T [b,d,t] fp16
__device__ __half g_Qh[BATCH*NH*SEQ*HD];     // Q  [b,h,s,d] fp16 (pre-scaled)
__device__ __half g_Zch[BATCH*SEQ*NH*HD];    // concat heads [b,s,h*d] fp16

#define SW128(off) ((off) ^ (((off) >> 3) & 0x70))

__device__ __forceinline__ uint32_t smem_u32(const void* p) {
    uint32_t a;
    asm("{ .reg .u64 t; cvta.to.shared.u64 t, %1; cvt.u32.u64 %0, t; }" : "=r"(a) : "l"(p));
    return a;
}
__device__ __forceinline__ void mma16816(float c[4], const uint32_t a[4], const uint32_t b[2]) {
    asm volatile("mma.sync.aligned.m16n8k16.row.col.f32.f16.f16.f32 "
        "{%0,%1,%2,%3}, {%4,%5,%6,%7}, {%8,%9}, {%0,%1,%2,%3};"
        : "+f"(c[0]), "+f"(c[1]), "+f"(c[2]), "+f"(c[3])
        : "r"(a[0]), "r"(a[1]), "r"(a[2]), "r"(a[3]), "r"(b[0]), "r"(b[1]));
}
// fp16-accumulated MMA: c-frag (2 regs) doubles as the P a-frag after in-place exp
__device__ __forceinline__ void mma16816_f16(uint32_t c[2], const uint32_t a[4], const uint32_t b[2]) {
    asm volatile("mma.sync.aligned.m16n8k16.row.col.f16.f16.f16.f16 "
        "{%0,%1}, {%2,%3,%4,%5}, {%6,%7}, {%0,%1};"
        : "+r"(c[0]), "+r"(c[1])
        : "r"(a[0]), "r"(a[1]), "r"(a[2]), "r"(a[3]), "r"(b[0]), "r"(b[1]));
}
__device__ __forceinline__ void ldsm_x4(uint32_t d[4], uint32_t addr) {
    asm volatile("ldmatrix.sync.aligned.m8n8.x4.shared.b16 {%0,%1,%2,%3}, [%4];"
        : "=r"(d[0]), "=r"(d[1]), "=r"(d[2]), "=r"(d[3]) : "r"(addr));
}
__device__ __forceinline__ void cp16(uint32_t sdst, const void* gsrc) {
    asm volatile("cp.async.cg.shared.global [%0], [%1], 16;" :: "r"(sdst), "l"(gsrc));
}
#define CP_COMMIT() asm volatile("cp.async.commit_group;" ::: "memory")
#define CP_WAIT(n)  asm volatile("cp.async.wait_group %0;" :: "n"(n) : "memory")

// ---------------- kernel 1: merged prep (x-convert + weight transposes + bias) ----------------
// grid = 2048 (x) + 352 (11 slabs x 32 tiles) + 1 (bias) = 2401 blocks, 256 thr.
__global__ __launch_bounds__(256) void prep2_kernel(
    const float* __restrict__ x,
    const float* __restrict__ Wk, const float* __restrict__ bk,
    const float* __restrict__ Wv, const float* __restrict__ bv,
    const float* __restrict__ Wq, const float* __restrict__ bq,
    const float* __restrict__ Wp)
{
    const int bid = blockIdx.x;
    const int tid = threadIdx.x;

    if (bid < 2048) {
        // x -> fp16, 8 elements per thread
        int idx = bid * 256 + tid;
        float4 a = *(const float4*)(x + idx*8);
        float4 b = *(const float4*)(x + idx*8 + 4);
        __half2 h[4] = { __floats2half2_rn(a.x, a.y), __floats2half2_rn(a.z, a.w),
                         __floats2half2_rn(b.x, b.y), __floats2half2_rn(b.z, b.w) };
        *(uint2*)(g_xh + idx*8)     = *(uint2*)&h[0];
        *(uint2*)(g_xh + idx*8 + 4) = *(uint2*)&h[2];
        return;
    }
    if (bid < 2048 + 352) {
        // weight transpose: slab of [512 k][64 n] -> fp16 [n][k]
        __shared__ float t[32][33];
        int bid2 = bid - 2048;
        int slab = bid2 >> 5, tt = bid2 & 31;
        int k0 = (tt & 15) * 32, n0 = (tt >> 4) * 32;
        const float* src;
        __half* dst;
        if (slab == 0)      src = Wk;
        else if (slab == 1) src = Wv;
        else if (slab < 10) src = Wq + (size_t)(slab-2)*WRD*HD;
        else                src = Wp;
        dst = (slab < 10) ? (g_WhT + (size_t)slab*64*WRD) : g_WpT;

        int tx = tid & 31, ty = tid >> 5;   // 32 x 8
        #pragma unroll
        for (int r = 0; r < 4; r++)
            t[ty + r*8][tx] = src[(size_t)(k0 + ty + r*8)*HD + n0 + tx];
        __syncthreads();
        #pragma unroll
        for (int r = 0; r < 4; r++) {
            int n = ty + r*8;
            dst[(size_t)(n0 + n)*WRD + k0 + tx] = __float2half_rn(t[tx][n]);
        }
        return;
    }
    // bias pack
    for (int i = tid; i < NQKV; i += 256) {
        float v;
        if (i < 64)       v = bk[i];
        else if (i < 128) v = bv[i-64];
        else              v = bq[i-128];
        g_ball[i] = v;
    }
}

// ---------------- kernel 2: QKV projection, m32 warp tiles, cp.async double-buffered ----------------
// grid (64, 10), 128 thr (4 warps x 32 m-rows). Tile 128m x 64n, K-step 64. 48KB static smem.
__global__ __launch_bounds__(128) void qkv_mma_kernel()
{
    __shared__ __align__(128) char sA[2][128*128];   // 2 x 16KB
    __shared__ __align__(128) char sB[2][64*128];    // 2 x  8KB

    const int tid = threadIdx.x;
    const int wid = tid >> 5, lane = tid & 31;
    const int m0 = blockIdx.x * 128, n0 = blockIdx.y * 64;

    auto load_tiles = [&](int buf, int k0) {
        #pragma unroll
        for (int r = 0; r < 8; r++) {
            int i = tid + r*128;
            int row = i >> 3, c8 = (i & 7) * 8;
            cp16(smem_u32(sA[buf]) + SW128((uint32_t)(row*128 + c8*2)),
                 g_xh + (size_t)(m0 + row)*WRD + k0 + c8);
        }
        #pragma unroll
        for (int r = 0; r < 4; r++) {
            int i = tid + r*128;
            int row = i >> 3, c8 = (i & 7) * 8;
            cp16(smem_u32(sB[buf]) + SW128((uint32_t)(row*128 + c8*2)),
                 g_WhT + (size_t)(n0 + row)*WRD + k0 + c8);
        }
    };

    float acc[2][8][4] = {};
    const uint32_t colb = (uint32_t)((lane & 8) ? 16 : 0);
    const uint32_t rwb  = (uint32_t)(((lane & 16) ? 8 : 0) + (lane & 7));

    load_tiles(0, 0); CP_COMMIT();

    for (int ki = 0; ki < 8; ki++) {
        if (ki < 7) { load_tiles((ki+1)&1, (ki+1)*64); CP_COMMIT(); CP_WAIT(1); }
        else CP_WAIT(0);
        __syncthreads();

        const uint32_t ab = smem_u32(sA[ki&1]), bb = smem_u32(sB[ki&1]);
        #pragma unroll
        for (int kk = 0; kk < 4; kk++) {
            uint32_t afr[2][4];
            #pragma unroll
            for (int a = 0; a < 2; a++) {
                int row = wid*32 + a*16 + (lane & 7) + ((lane >> 3) & 1) * 8;
                uint32_t col = (uint32_t)(kk*32 + ((lane >> 4) ? 16 : 0));
                ldsm_x4(afr[a], ab + SW128((uint32_t)row*128 + col));
            }
            uint32_t cc = (uint32_t)(kk*32) + colb;
            #pragma unroll
            for (int j2 = 0; j2 < 4; j2++) {
                uint32_t bfr[4];
                ldsm_x4(bfr, bb + SW128((j2*16 + rwb)*128 + cc));
                #pragma unroll
                for (int a = 0; a < 2; a++) {
                    mma16816(acc[a][2*j2],   afr[a], bfr);
                    mma16816(acc[a][2*j2+1], afr[a], bfr + 2);
                }
            }
        }
        __syncthreads();
    }

    // ---- epilogue: bias + scatter to K / V^T / Q ----
    #pragma unroll
    for (int a = 0; a < 2; a++) {
        int r = wid*32 + a*16 + (lane >> 2);
        #pragma unroll
        for (int j = 0; j < 8; j++) {
            #pragma unroll
            for (int e = 0; e < 2; e++) {
                int n = n0 + j*8 + (lane & 3)*2 + e;
                float bias = g_ball[n];
                #pragma unroll
                for (int rr = 0; rr < 2; rr++) {
                    int m = m0 + r + rr*8;
                    float v = acc[a][j][rr*2 + e] + bias;
                    int b = m >> 12, s = m & 4095;
                    if (n < 64) {
                        g_Kh[((size_t)b*SEQ + s)*HD + n] = __float2half_rn(v);
                    } else if (n < 128) {
                        g_Vth[((size_t)b*HD + (n-64))*SEQ + s] = __float2half_rn(v);
                    } else {
                        int nn = n - 128; int h = nn >> 6, d = nn & 63;
                        g_Qh[(((size_t)b*NH + h)*SEQ + s)*HD + d] = __float2half_rn(v * QSCALE);
                    }
                }
            }
        }
    }
}

// ---------------- kernel 3: mma.sync flash attention, 128-key steps, 3-slot dynamic ring ----------------
// (frozen: round-13 best config)
__global__ __launch_bounds__(128, 2) void attn_mma_kernel()
{
    extern __shared__ __align__(128) char smemAll[];   // 3 x 32768; slot2 doubles as Q staging

    const int tid  = threadIdx.x;
    const int wid  = tid >> 5, lane = tid & 31;
    const int b = blockIdx.z, hh = blockIdx.y, q0 = blockIdx.x * 128;

    const __half* Qp = g_Qh + ((size_t)(b*NH + hh)*SEQ + q0) * HD;
    const __half* Kp = g_Kh  + (size_t)b*SEQ*HD;
    const __half* Vp = g_Vth + (size_t)b*HD*SEQ;

    auto kbuf = [&](int r) -> char* { return smemAll + r*32768; };
    auto vbuf = [&](int r) -> char* { return smemAll + r*32768 + 16384; };
    char* sQ = smemAll + 2*32768;

    auto load_kv = [&](int slot, int kt) {
        char* kb = kbuf(slot); char* vb = vbuf(slot);
        #pragma unroll
        for (int r = 0; r < 8; r++) {
            int i = tid + r*128;
            int row = i >> 3, c8 = (i & 7) * 8;
            cp16(smem_u32(kb) + SW128((uint32_t)(row*128 + c8*2)),
                 Kp + (size_t)(kt*128 + row)*HD + c8);
        }
        #pragma unroll
        for (int r = 0; r < 8; r++) {
            int i = tid + r*128;
            int d = i >> 4, t16 = (i & 15) * 8;
            int sub = t16 >> 6, tloc = t16 & 63;
            cp16(smem_u32(vb) + (uint32_t)(sub*8192) + SW128((uint32_t)(d*128 + tloc*2)),
                 Vp + (size_t)d*SEQ + kt*128 + t16);
        }
    };

    load_kv(0, 0); CP_COMMIT();
    load_kv(1, 1); CP_COMMIT();

    #pragma unroll
    for (int r = 0; r < 8; r++) {
        int i = tid + r*128;
        int row = i >> 3, c8 = (i & 7) * 8;
        *(uint4*)(sQ + SW128((uint32_t)(row*128 + c8*2))) = *(const uint4*)(Qp + row*HD + c8);
    }
    __syncthreads();
    uint32_t qa[2][4][4];
    {
        const uint32_t qb = smem_u32(sQ);
        #pragma unroll
        for (int a = 0; a < 2; a++) {
            int row = wid*32 + a*16 + (lane & 7) + ((lane >> 3) & 1) * 8;
            #pragma unroll
            for (int kk = 0; kk < 4; kk++) {
                uint32_t col = (uint32_t)(kk*32 + ((lane >> 4) ? 16 : 0));
                ldsm_x4(qa[a][kk], qb + SW128((uint32_t)row*128 + col));
            }
        }
    }

    float oc[2][8][4] = {};
    float lsacc[2][4] = {};
    const uint32_t ones_frag[2] = { 0x3C003C00u, 0x3C003C00u };  // fp16 1.0 x4
    const uint32_t colb = (uint32_t)((lane & 8) ? 16 : 0);
    const uint32_t rwb  = (uint32_t)(((lane & 16) ? 8 : 0) + (lane & 7));

    for (int kt = 0; kt < NKT2; kt++) {
        CP_WAIT(0);
        __syncthreads();
        if (kt + 2 < NKT2) { load_kv((kt+2)%3, kt+2); CP_COMMIT(); }

        const uint32_t kb_ = smem_u32(kbuf(kt%3));
        const uint32_t vb_ = smem_u32(vbuf(kt%3));

        uint32_t scf[2][16][2];
        #pragma unroll
        for (int a = 0; a < 2; a++)
            #pragma unroll
            for (int j = 0; j < 16; j++) { scf[a][j][0] = 0u; scf[a][j][1] = 0u; }
        #pragma unroll
        for (int kk = 0; kk < 4; kk++) {
            uint32_t cc = (uint32_t)(kk*32) + colb;
            #pragma unroll
            for (int j2 = 0; j2 < 8; j2++) {
                uint32_t bfr[4];
                ldsm_x4(bfr, kb_ + SW128((uint32_t)(j2*16 + rwb)*128 + cc));
                #pragma unroll
                for (int a = 0; a < 2; a++) {
                    mma16816_f16(scf[a][2*j2],   qa[a][kk], bfr);
                    mma16816_f16(scf[a][2*j2+1], qa[a][kk], bfr + 2);
                }
            }
        }

        #pragma unroll
        for (int tt = 0; tt < 8; tt++) {
            uint32_t pa[2][4];
            #pragma unroll
            for (int a = 0; a < 2; a++) {
                __half2 e0 = h2exp2(*(__half2*)&scf[a][2*tt][0]);
                __half2 e1 = h2exp2(*(__half2*)&scf[a][2*tt][1]);
                __half2 e2 = h2exp2(*(__half2*)&scf[a][2*tt+1][0]);
                __half2 e3 = h2exp2(*(__half2*)&scf[a][2*tt+1][1]);
                pa[a][0] = *(uint32_t*)&e0;
                pa[a][1] = *(uint32_t*)&e1;
                pa[a][2] = *(uint32_t*)&e2;
                pa[a][3] = *(uint32_t*)&e3;
            }
            uint32_t vblk = vb_ + (uint32_t)((tt >> 2)*8192);
            uint32_t cc = (uint32_t)((tt & 3)*32) + colb;
            #pragma unroll
            for (int jv = 0; jv < 4; jv++) {
                uint32_t bfr[4];
                ldsm_x4(bfr, vblk + SW128((uint32_t)(jv*16 + rwb)*128 + cc));
                #pragma unroll
                for (int a = 0; a < 2; a++) {
                    mma16816(oc[a][2*jv],   pa[a], bfr);
                    mma16816(oc[a][2*jv+1], pa[a], bfr + 2);
                }
            }
            #pragma unroll
            for (int a = 0; a < 2; a++)
                mma16816(lsacc[a], pa[a], ones_frag);
        }
    }

    int c0 = (lane & 3) * 2;
    #pragma unroll
    for (int a = 0; a < 2; a++) {
        float inv0 = 1.0f / lsacc[a][0], inv1 = 1.0f / lsacc[a][2];
        int r = wid*32 + a*16 + (lane >> 2);
        __half* Z0 = g_Zch + ((size_t)(b*SEQ) + q0 + r    )*(NH*HD) + hh*HD;
        __half* Z1 = g_Zch + ((size_t)(b*SEQ) + q0 + r + 8)*(NH*HD) + hh*HD;
        #pragma unroll
        for (int j = 0; j < 8; j++) {
            int d = j*8 + c0;
            *(__half2*)(Z0 + d) = __floats2half2_rn(oc[a][j][0]*inv0, oc[a][j][1]*inv0);
            *(__half2*)(Z1 + d) = __floats2half2_rn(oc[a][j][2]*inv1, oc[a][j][3]*inv1);
        }
    }
}

// ---------------- kernel 4: output projection, m32 warp tiles, cp.async double-buffered ----------------
// grid (64), 128 thr (4 warps x 32 m-rows). Tile 128m x 64n, K-step 64. 48KB static smem.
__global__ __launch_bounds__(128) void oproj_mma_kernel(const float* __restrict__ bp,
                                                        float* __restrict__ out)
{
    __shared__ __align__(128) char sA[2][128*128];   // 2 x 16KB
    __shared__ __align__(128) char sB[2][64*128];    // 2 x  8KB

    const int tid = threadIdx.x;
    const int wid = tid >> 5, lane = tid & 31;
    const int m0 = blockIdx.x * 128;

    auto load_tiles = [&](int buf, int k0) {
        #pragma unroll
        for (int r = 0; r < 8; r++) {
            int i = tid + r*128;
            int row = i >> 3, c8 = (i & 7) * 8;
            cp16(smem_u32(sA[buf]) + SW128((uint32_t)(row*128 + c8*2)),
                 g_Zch + (size_t)(m0 + row)*WRD + k0 + c8);
        }
        #pragma unroll
        for (int r = 0; r < 4; r++) {
            int i = tid + r*128;
            int row = i >> 3, c8 = (i & 7) * 8;
            cp16(smem_u32(sB[buf]) + SW128((uint32_t)(row*128 + c8*2)),
                 g_WpT + (size_t)row*WRD + k0 + c8);
        }
    };

    float acc[2][8][4] = {};
    const uint32_t colb = (uint32_t)((lane & 8) ? 16 : 0);
    const uint32_t rwb  = (uint32_t)(((lane & 16) ? 8 : 0) + (lane & 7));

    load_tiles(0, 0); CP_COMMIT();

    for (int ki = 0; ki < 8; ki++) {
        if (ki < 7) { load_tiles((ki+1)&1, (ki+1)*64); CP_COMMIT(); CP_WAIT(1); }
        else CP_WAIT(0);
        __syncthreads();

        const uint32_t ab = smem_u32(sA[ki&1]), bb = smem_u32(sB[ki&1]);
        #pragma unroll
        for (int kk = 0; kk < 4; kk++) {
            uint32_t afr[2][4];
            #pragma unroll
            for (int a = 0; a < 2; a++) {
                int row = wid*32 + a*16 + (lane & 7) + ((lane >> 3) & 1) * 8;
                uint32_t col = (uint32_t)(kk*32 + ((lane >> 4) ? 16 : 0));
                ldsm_x4(afr[a], ab + SW128((uint32_t)row*128 + col));
            }
            uint32_t cc = (uint32_t)(kk*32) + colb;
            #pragma unroll
            for (int j2 = 0; j2 < 4; j2++) {
                uint32_t bfr[4];
                ldsm_x4(bfr, bb + SW128((j2*16 + rwb)*128 + cc));
                #pragma unroll
                for (int a = 0; a < 2; a++) {
                    mma16816(acc[a][2*j2],   afr[a], bfr);
                    mma16816(acc[a][2*j2+1], afr[a], bfr + 2);
                }
            }
        }
        __syncthreads();
    }

    int c0 = (lane & 3) * 2;
    #pragma unroll
    for (int a = 0; a < 2; a++) {
        int r = wid*32 + a*16 + (lane >> 2);
        float* O0 = out + (size_t)(m0 + r    )*HD;
        float* O1 = out + (size_t)(m0 + r + 8)*HD;
        #pragma unroll
        for (int j = 0; j < 8; j++) {
            int n = j*8 + c0;
            float b0 = bp[n], b1 = bp[n+1];
            *(float2*)(O0 + n) = make_float2(acc[a][j][0] + b0, acc[a][j][1] + b1);
            *(float2*)(O1 + n) = make_float2(acc[a][j][2] + b0, acc[a][j][3] + b1);
        }
    }
}

// ---------------- launch ----------------
extern "C" void kernel_launch(void* const* d_in, const int* in_sizes, int n_in,
                              void* d_out, int out_size)
{
    const float* x  = (const float*)d_in[0];
    const float* Wq = (const float*)d_in[1];
    const float* bq = (const float*)d_in[2];
    const float* Wk = (const float*)d_in[3];
    const float* bk = (const float*)d_in[4];
    const float* Wv = (const float*)d_in[5];
    const float* bv = (const float*)d_in[6];
    const float* Wp = (const float*)d_in[7];
    const float* bp = (const float*)d_in[8];
    float* out = (float*)d_out;

    prep2_kernel<<<2048 + 352 + 1, 256>>>(x, Wk, bk, Wv, bv, Wq, bq, Wp);

    qkv_mma_kernel<<<dim3(MTOT/128, NQKV/64), 128>>>();

    const int attn_smem = 3 * 32768;   // 96KB dynamic ring
    cudaFuncSetAttribute(attn_mma_kernel, cudaFuncAttributeMaxDynamicSharedMemorySize, attn_smem);
    attn_mma_kernel<<<dim3(SEQ/128, NH, BATCH), 128, attn_smem>>>();

    oproj_mma_kernel<<<dim3(MTOT/128), 128>>>(bp, out);
}

// round 15
// speedup vs baseline: 1.0258x; 1.0070x over previous
#include <cuda_runtime.h>
#include <cuda_fp16.h>
#include <math.h>
#include <cstdint>

#define BATCH 2
#define NH    8
#define SEQ   4096
#define HD    64
#define WRD   512
#define MTOT  (BATCH*SEQ)     // 8192
#define NQKV  640             // 64 (K) + 64 (V) + 8*64 (Q)
#define NKT2  (SEQ/128)       // 32 key tiles of 128

// Q pre-scale: (1/sqrt(64)) * log2(e)  -> scores in log2 domain, exp2 for softmax
#define QSCALE 0.18033688011112042f

// ---------------- scratch (device globals; no allocation allowed) ----------------
__device__ __half g_xh[MTOT*WRD];            // x fp16 [8192,512]
__device__ __half g_WhT[NQKV*WRD];           // packed QKV weight, transposed [n][k] fp16
__device__ __half g_WpT[HD*WRD];             // Wp transposed [n][k] fp16
__device__ float  g_ball[NQKV];              // packed QKV bias fp32
__device__ __half g_Kh[BATCH*SEQ*HD];        // K  [b,t,d] fp16
__device__ __half g_Vth[BATCH*HD*SEQ];       // V^T [b,d,t] fp16
__device__ __half g_Qh[BATCH*NH*SEQ*HD];     // Q  [b,h,s,d] fp16 (pre-scaled)

#define SW128(off) ((off) ^ (((off) >> 3) & 0x70))

__device__ __forceinline__ uint32_t smem_u32(const void* p) {
    uint32_t a;
    asm("{ .reg .u64 t; cvta.to.shared.u64 t, %1; cvt.u32.u64 %0, t; }" : "=r"(a) : "l"(p));
    return a;
}
__device__ __forceinline__ void mma16816(float c[4], const uint32_t a[4], const uint32_t b[2]) {
    asm volatile("mma.sync.aligned.m16n8k16.row.col.f32.f16.f16.f32 "
        "{%0,%1,%2,%3}, {%4,%5,%6,%7}, {%8,%9}, {%0,%1,%2,%3};"
        : "+f"(c[0]), "+f"(c[1]), "+f"(c[2]), "+f"(c[3])
        : "r"(a[0]), "r"(a[1]), "r"(a[2]), "r"(a[3]), "r"(b[0]), "r"(b[1]));
}
// fp16-accumulated MMA: c-frag (2 regs) doubles as the P a-frag after in-place exp
__device__ __forceinline__ void mma16816_f16(uint32_t c[2], const uint32_t a[4], const uint32_t b[2]) {
    asm volatile("mma.sync.aligned.m16n8k16.row.col.f16.f16.f16.f16 "
        "{%0,%1}, {%2,%3,%4,%5}, {%6,%7}, {%0,%1};"
        : "+r"(c[0]), "+r"(c[1])
        : "r"(a[0]), "r"(a[1]), "r"(a[2]), "r"(a[3]), "r"(b[0]), "r"(b[1]));
}
__device__ __forceinline__ void ldsm_x4(uint32_t d[4], uint32_t addr) {
    asm volatile("ldmatrix.sync.aligned.m8n8.x4.shared.b16 {%0,%1,%2,%3}, [%4];"
        : "=r"(d[0]), "=r"(d[1]), "=r"(d[2]), "=r"(d[3]) : "r"(addr));
}
__device__ __forceinline__ void cp16(uint32_t sdst, const void* gsrc) {
    asm volatile("cp.async.cg.shared.global [%0], [%1], 16;" :: "r"(sdst), "l"(gsrc));
}
#define CP_COMMIT() asm volatile("cp.async.commit_group;" ::: "memory")
#define CP_WAIT(n)  asm volatile("cp.async.wait_group %0;" :: "n"(n) : "memory")

// ---------------- kernel 1: merged prep (x-convert + transposes + bias + out-init) ----------------
// grid = 2048 (x) + 352 (transpose) + 1 (bias) + 512 (out init) = 2913 blocks, 256 thr.
__global__ __launch_bounds__(256) void prep2_kernel(
    const float* __restrict__ x,
    const float* __restrict__ Wk, const float* __restrict__ bk,
    const float* __restrict__ Wv, const float* __restrict__ bv,
    const float* __restrict__ Wq, const float* __restrict__ bq,
    const float* __restrict__ Wp, const float* __restrict__ bp,
    float* __restrict__ out)
{
    const int bid = blockIdx.x;
    const int tid = threadIdx.x;

    if (bid < 2048) {
        // x -> fp16, 8 elements per thread
        int idx = bid * 256 + tid;
        float4 a = *(const float4*)(x + idx*8);
        float4 b = *(const float4*)(x + idx*8 + 4);
        __half2 h[4] = { __floats2half2_rn(a.x, a.y), __floats2half2_rn(a.z, a.w),
                         __floats2half2_rn(b.x, b.y), __floats2half2_rn(b.z, b.w) };
        *(uint2*)(g_xh + idx*8)     = *(uint2*)&h[0];
        *(uint2*)(g_xh + idx*8 + 4) = *(uint2*)&h[2];
        return;
    }
    if (bid < 2048 + 352) {
        // weight transpose: slab of [512 k][64 n] -> fp16 [n][k]
        __shared__ float t[32][33];
        int bid2 = bid - 2048;
        int slab = bid2 >> 5, tt = bid2 & 31;
        int k0 = (tt & 15) * 32, n0 = (tt >> 4) * 32;
        const float* src;
        __half* dst;
        if (slab == 0)      src = Wk;
        else if (slab == 1) src = Wv;
        else if (slab < 10) src = Wq + (size_t)(slab-2)*WRD*HD;
        else                src = Wp;
        dst = (slab < 10) ? (g_WhT + (size_t)slab*64*WRD) : g_WpT;

        int tx = tid & 31, ty = tid >> 5;   // 32 x 8
        #pragma unroll
        for (int r = 0; r < 4; r++)
            t[ty + r*8][tx] = src[(size_t)(k0 + ty + r*8)*HD + n0 + tx];
        __syncthreads();
        #pragma unroll
        for (int r = 0; r < 4; r++) {
            int n = ty + r*8;
            dst[(size_t)(n0 + n)*WRD + k0 + tx] = __float2half_rn(t[tx][n]);
        }
        return;
    }
    if (bid == 2048 + 352) {
        // bias pack
        for (int i = tid; i < NQKV; i += 256) {
            float v;
            if (i < 64)       v = bk[i];
            else if (i < 128) v = bv[i-64];
            else              v = bq[i-128];
            g_ball[i] = v;
        }
        return;
    }
    // out init: out[m][n] = bp[n]  (heads atomically accumulate on top)
    {
        int idx = (bid - 2049 - 352) * 256 + tid;    // float4 index, 131072 total
        int col = (idx & 15) * 4;
        float4 bv4 = *(const float4*)(bp + col);
        *(float4*)(out + (size_t)idx*4) = bv4;
    }
}

// ---------------- kernel 2: QKV projection, m32 warp tiles, cp.async double-buffered ----------------
// grid (64, 10), 128 thr (4 warps x 32 m-rows). Tile 128m x 64n, K-step 64. 48KB static smem.
__global__ __launch_bounds__(128) void qkv_mma_kernel()
{
    __shared__ __align__(128) char sA[2][128*128];   // 2 x 16KB
    __shared__ __align__(128) char sB[2][64*128];    // 2 x  8KB

    const int tid = threadIdx.x;
    const int wid = tid >> 5, lane = tid & 31;
    const int m0 = blockIdx.x * 128, n0 = blockIdx.y * 64;

    auto load_tiles = [&](int buf, int k0) {
        #pragma unroll
        for (int r = 0; r < 8; r++) {
            int i = tid + r*128;
            int row = i >> 3, c8 = (i & 7) * 8;
            cp16(smem_u32(sA[buf]) + SW128((uint32_t)(row*128 + c8*2)),
                 g_xh + (size_t)(m0 + row)*WRD + k0 + c8);
        }
        #pragma unroll
        for (int r = 0; r < 4; r++) {
            int i = tid + r*128;
            int row = i >> 3, c8 = (i & 7) * 8;
            cp16(smem_u32(sB[buf]) + SW128((uint32_t)(row*128 + c8*2)),
                 g_WhT + (size_t)(n0 + row)*WRD + k0 + c8);
        }
    };

    float acc[2][8][4] = {};
    const uint32_t colb = (uint32_t)((lane & 8) ? 16 : 0);
    const uint32_t rwb  = (uint32_t)(((lane & 16) ? 8 : 0) + (lane & 7));

    load_tiles(0, 0); CP_COMMIT();

    for (int ki = 0; ki < 8; ki++) {
        if (ki < 7) { load_tiles((ki+1)&1, (ki+1)*64); CP_COMMIT(); CP_WAIT(1); }
        else CP_WAIT(0);
        __syncthreads();

        const uint32_t ab = smem_u32(sA[ki&1]), bb = smem_u32(sB[ki&1]);
        #pragma unroll
        for (int kk = 0; kk < 4; kk++) {
            uint32_t afr[2][4];
            #pragma unroll
            for (int a = 0; a < 2; a++) {
                int row = wid*32 + a*16 + (lane & 7) + ((lane >> 3) & 1) * 8;
                uint32_t col = (uint32_t)(kk*32 + ((lane >> 4) ? 16 : 0));
                ldsm_x4(afr[a], ab + SW128((uint32_t)row*128 + col));
            }
            uint32_t cc = (uint32_t)(kk*32) + colb;
            #pragma unroll
            for (int j2 = 0; j2 < 4; j2++) {
                uint32_t bfr[4];
                ldsm_x4(bfr, bb + SW128((j2*16 + rwb)*128 + cc));
                #pragma unroll
                for (int a = 0; a < 2; a++) {
                    mma16816(acc[a][2*j2],   afr[a], bfr);
                    mma16816(acc[a][2*j2+1], afr[a], bfr + 2);
                }
            }
        }
        __syncthreads();
    }

    // ---- epilogue: bias + scatter to K / V^T / Q ----
    #pragma unroll
    for (int a = 0; a < 2; a++) {
        int r = wid*32 + a*16 + (lane >> 2);
        #pragma unroll
        for (int j = 0; j < 8; j++) {
            #pragma unroll
            for (int e = 0; e < 2; e++) {
                int n = n0 + j*8 + (lane & 3)*2 + e;
                float bias = g_ball[n];
                #pragma unroll
                for (int rr = 0; rr < 2; rr++) {
                    int m = m0 + r + rr*8;
                    float v = acc[a][j][rr*2 + e] + bias;
                    int b = m >> 12, s = m & 4095;
                    if (n < 64) {
                        g_Kh[((size_t)b*SEQ + s)*HD + n] = __float2half_rn(v);
                    } else if (n < 128) {
                        g_Vth[((size_t)b*HD + (n-64))*SEQ + s] = __float2half_rn(v);
                    } else {
                        int nn = n - 128; int h = nn >> 6, d = nn & 63;
                        g_Qh[(((size_t)b*NH + h)*SEQ + s)*HD + d] = __float2half_rn(v * QSCALE);
                    }
                }
            }
        }
    }
}

// ---------------- kernel 3: flash attention + fused output projection ----------------
// grid (SEQ/128, NH, BATCH), 128 threads = 4 warps x 32 q-rows, 2 CTAs/SM.
// Mainloop frozen (round-13 config). Epilogue: normalize O in fp16 a-frags, multiply by
// this head's Wp k-slice (ldsm from reused ring smem), atomicAdd partial into out
// (pre-initialized with bias by prep2).
__global__ __launch_bounds__(128, 2) void attn_mma_kernel(float* __restrict__ out)
{
    extern __shared__ __align__(128) char smemAll[];   // 3 x 32768; slot2 doubles as Q staging

    const int tid  = threadIdx.x;
    const int wid  = tid >> 5, lane = tid & 31;
    const int b = blockIdx.z, hh = blockIdx.y, q0 = blockIdx.x * 128;

    const __half* Qp = g_Qh + ((size_t)(b*NH + hh)*SEQ + q0) * HD;
    const __half* Kp = g_Kh  + (size_t)b*SEQ*HD;
    const __half* Vp = g_Vth + (size_t)b*HD*SEQ;

    auto kbuf = [&](int r) -> char* { return smemAll + r*32768; };
    auto vbuf = [&](int r) -> char* { return smemAll + r*32768 + 16384; };
    char* sQ = smemAll + 2*32768;

    auto load_kv = [&](int slot, int kt) {
        char* kb = kbuf(slot); char* vb = vbuf(slot);
        #pragma unroll
        for (int r = 0; r < 8; r++) {
            int i = tid + r*128;
            int row = i >> 3, c8 = (i & 7) * 8;
            cp16(smem_u32(kb) + SW128((uint32_t)(row*128 + c8*2)),
                 Kp + (size_t)(kt*128 + row)*HD + c8);
        }
        #pragma unroll
        for (int r = 0; r < 8; r++) {
            int i = tid + r*128;
            int d = i >> 4, t16 = (i & 15) * 8;
            int sub = t16 >> 6, tloc = t16 & 63;
            cp16(smem_u32(vb) + (uint32_t)(sub*8192) + SW128((uint32_t)(d*128 + tloc*2)),
                 Vp + (size_t)d*SEQ + kt*128 + t16);
        }
    };

    load_kv(0, 0); CP_COMMIT();
    load_kv(1, 1); CP_COMMIT();

    #pragma unroll
    for (int r = 0; r < 8; r++) {
        int i = tid + r*128;
        int row = i >> 3, c8 = (i & 7) * 8;
        *(uint4*)(sQ + SW128((uint32_t)(row*128 + c8*2))) = *(const uint4*)(Qp + row*HD + c8);
    }
    __syncthreads();
    uint32_t qa[2][4][4];
    {
        const uint32_t qb = smem_u32(sQ);
        #pragma unroll
        for (int a = 0; a < 2; a++) {
            int row = wid*32 + a*16 + (lane & 7) + ((lane >> 3) & 1) * 8;
            #pragma unroll
            for (int kk = 0; kk < 4; kk++) {
                uint32_t col = (uint32_t)(kk*32 + ((lane >> 4) ? 16 : 0));
                ldsm_x4(qa[a][kk], qb + SW128((uint32_t)row*128 + col));
            }
        }
    }

    float oc[2][8][4] = {};
    float lsacc[2][4] = {};
    const uint32_t ones_frag[2] = { 0x3C003C00u, 0x3C003C00u };  // fp16 1.0 x4
    const uint32_t colb = (uint32_t)((lane & 8) ? 16 : 0);
    const uint32_t rwb  = (uint32_t)(((lane & 16) ? 8 : 0) + (lane & 7));

    for (int kt = 0; kt < NKT2; kt++) {
        CP_WAIT(0);
        __syncthreads();
        if (kt + 2 < NKT2) { load_kv((kt+2)%3, kt+2); CP_COMMIT(); }

        const uint32_t kb_ = smem_u32(kbuf(kt%3));
        const uint32_t vb_ = smem_u32(vbuf(kt%3));

        uint32_t scf[2][16][2];
        #pragma unroll
        for (int a = 0; a < 2; a++)
            #pragma unroll
            for (int j = 0; j < 16; j++) { scf[a][j][0] = 0u; scf[a][j][1] = 0u; }
        #pragma unroll
        for (int kk = 0; kk < 4; kk++) {
            uint32_t cc = (uint32_t)(kk*32) + colb;
            #pragma unroll
            for (int j2 = 0; j2 < 8; j2++) {
                uint32_t bfr[4];
                ldsm_x4(bfr, kb_ + SW128((uint32_t)(j2*16 + rwb)*128 + cc));
                #pragma unroll
                for (int a = 0; a < 2; a++) {
                    mma16816_f16(scf[a][2*j2],   qa[a][kk], bfr);
                    mma16816_f16(scf[a][2*j2+1], qa[a][kk], bfr + 2);
                }
            }
        }

        #pragma unroll
        for (int tt = 0; tt < 8; tt++) {
            uint32_t pa[2][4];
            #pragma unroll
            for (int a = 0; a < 2; a++) {
                __half2 e0 = h2exp2(*(__half2*)&scf[a][2*tt][0]);
                __half2 e1 = h2exp2(*(__half2*)&scf[a][2*tt][1]);
                __half2 e2 = h2exp2(*(__half2*)&scf[a][2*tt+1][0]);
                __half2 e3 = h2exp2(*(__half2*)&scf[a][2*tt+1][1]);
                pa[a][0] = *(uint32_t*)&e0;
                pa[a][1] = *(uint32_t*)&e1;
                pa[a][2] = *(uint32_t*)&e2;
                pa[a][3] = *(uint32_t*)&e3;
            }
            uint32_t vblk = vb_ + (uint32_t)((tt >> 2)*8192);
            uint32_t cc = (uint32_t)((tt & 3)*32) + colb;
            #pragma unroll
            for (int jv = 0; jv < 4; jv++) {
                uint32_t bfr[4];
                ldsm_x4(bfr, vblk + SW128((uint32_t)(jv*16 + rwb)*128 + cc));
                #pragma unroll
                for (int a = 0; a < 2; a++) {
                    mma16816(oc[a][2*jv],   pa[a], bfr);
                    mma16816(oc[a][2*jv+1], pa[a], bfr + 2);
                }
            }
            #pragma unroll
            for (int a = 0; a < 2; a++)
                mma16816(lsacc[a], pa[a], ones_frag);
        }
    }

    // ---- fused output projection: out += (O/lsum) @ WpT[., hh*64 : hh*64+64] ----
    __syncthreads();   // ring buffers free
    {
        // stage Wp slice [64 n][64 k] fp16 into slot0 (8KB), SW128
        char* sW = kbuf(0);
        #pragma unroll
        for (int r = 0; r < 4; r++) {
            int i = tid + r*128;
            int row = i >> 3, c8 = (i & 7) * 8;
            cp16(smem_u32(sW) + SW128((uint32_t)(row*128 + c8*2)),
                 g_WpT + (size_t)row*WRD + hh*64 + c8);
        }
        CP_COMMIT(); CP_WAIT(0);
        __syncthreads();

        const uint32_t wb_ = smem_u32(sW);
        float outacc[2][8][4] = {};
        #pragma unroll
        for (int a = 0; a < 2; a++) {
            float inv0 = 1.0f / lsacc[a][0], inv1 = 1.0f / lsacc[a][2];
            #pragma unroll
            for (int kk = 0; kk < 4; kk++) {
                // a-frag from normalized O c-frags (layout-identical)
                uint32_t oa[4];
                __half2 h0 = __floats2half2_rn(oc[a][2*kk][0]*inv0,   oc[a][2*kk][1]*inv0);
                __half2 h1 = __floats2half2_rn(oc[a][2*kk][2]*inv1,   oc[a][2*kk][3]*inv1);
                __half2 h2_ = __floats2half2_rn(oc[a][2*kk+1][0]*inv0, oc[a][2*kk+1][1]*inv0);
                __half2 h3 = __floats2half2_rn(oc[a][2*kk+1][2]*inv1, oc[a][2*kk+1][3]*inv1);
                oa[0] = *(uint32_t*)&h0;
                oa[1] = *(uint32_t*)&h1;
                oa[2] = *(uint32_t*)&h2_;
                oa[3] = *(uint32_t*)&h3;
                uint32_t cc = (uint32_t)(kk*32) + colb;
                #pragma unroll
                for (int j2 = 0; j2 < 4; j2++) {
                    uint32_t bfr[4];
                    ldsm_x4(bfr, wb_ + SW128((uint32_t)(j2*16 + rwb)*128 + cc));
                    mma16816(outacc[a][2*j2],   oa, bfr);
                    mma16816(outacc[a][2*j2+1], oa, bfr + 2);
                }
            }
        }

        // atomic accumulate the head partial into out (bias pre-added by prep2)
        int c0 = (lane & 3) * 2;
        #pragma unroll
        for (int a = 0; a < 2; a++) {
            int r = wid*32 + a*16 + (lane >> 2);
            float* O0 = out + ((size_t)(b*SEQ) + q0 + r    )*HD;
            float* O1 = out + ((size_t)(b*SEQ) + q0 + r + 8)*HD;
            #pragma unroll
            for (int j = 0; j < 8; j++) {
                int n = j*8 + c0;
                atomicAdd(O0 + n,     outacc[a][j][0]);
                atomicAdd(O0 + n + 1, outacc[a][j][1]);
                atomicAdd(O1 + n,     outacc[a][j][2]);
                atomicAdd(O1 + n + 1, outacc[a][j][3]);
            }
        }
    }
}

// ---------------- launch ----------------
extern "C" void kernel_launch(void* const* d_in, const int* in_sizes, int n_in,
                              void* d_out, int out_size)
{
    const float* x  = (const float*)d_in[0];
    const float* Wq = (const float*)d_in[1];
    const float* bq = (const float*)d_in[2];
    const float* Wk = (const float*)d_in[3];
    const float* bk = (const float*)d_in[4];
    const float* Wv = (const float*)d_in[5];
    const float* bv = (const float*)d_in[6];
    const float* Wp = (const float*)d_in[7];
    const float* bp = (const float*)d_in[8];
    float* out = (float*)d_out;

    prep2_kernel<<<2048 + 352 + 1 + 512, 256>>>(x, Wk, bk, Wv, bv, Wq, bq, Wp, bp, out);

    qkv_mma_kernel<<<dim3(MTOT/128, NQKV/64), 128>>>();

    const int attn_smem = 3 * 32768;   // 96KB dynamic ring
    cudaFuncSetAttribute(attn_mma_kernel, cudaFuncAttributeMaxDynamicSharedMemorySize, attn_smem);
    attn_mma_kernel<<<dim3(SEQ/128, NH, BATCH), 128, attn_smem>>>(out);
}

// round 16
// speedup vs baseline: 1.0356x; 1.0096x over previous
#include <cuda_runtime.h>
#include <cuda_fp16.h>
#include <math.h>
#include <cstdint>

#define BATCH 2
#define NH    8
#define SEQ   4096
#define HD    64
#define WRD   512
#define MTOT  (BATCH*SEQ)     // 8192
#define NQKV  640             // 64 (K) + 64 (V) + 8*64 (Q)
#define NKT2  (SEQ/128)       // 32 key tiles of 128

// Q pre-scale: (1/sqrt(64)) * log2(e)  -> scores in log2 domain, exp2 for softmax
#define QSCALE 0.18033688011112042f

// ---------------- scratch (device globals; no allocation allowed) ----------------
__device__ __half g_xh[MTOT*WRD];            // x fp16 [8192,512]
__device__ __half g_WhT[NQKV*WRD];           // packed QKV weight, transposed [n][k] fp16
__device__ __half g_WpT[HD*WRD];             // Wp transposed [n][k] fp16
__device__ float  g_ball[NQKV];              // packed QKV bias fp32
__device__ __half g_Kh[BATCH*SEQ*HD];        // K  [b,t,d] fp16
__device__ __half g_Vth[BATCH*HD*SEQ];       // V^T [b,d,t] fp16
__device__ __half g_Qh[BATCH*NH*SEQ*HD];     // Q  [b,h,s,d] fp16 (pre-scaled)

#define SW128(off) ((off) ^ (((off) >> 3) & 0x70))

__device__ __forceinline__ uint32_t smem_u32(const void* p) {
    uint32_t a;
    asm("{ .reg .u64 t; cvta.to.shared.u64 t, %1; cvt.u32.u64 %0, t; }" : "=r"(a) : "l"(p));
    return a;
}
__device__ __forceinline__ void mma16816(float c[4], const uint32_t a[4], const uint32_t b[2]) {
    asm volatile("mma.sync.aligned.m16n8k16.row.col.f32.f16.f16.f32 "
        "{%0,%1,%2,%3}, {%4,%5,%6,%7}, {%8,%9}, {%0,%1,%2,%3};"
        : "+f"(c[0]), "+f"(c[1]), "+f"(c[2]), "+f"(c[3])
        : "r"(a[0]), "r"(a[1]), "r"(a[2]), "r"(a[3]), "r"(b[0]), "r"(b[1]));
}
// fp16-accumulated MMA: c-frag (2 regs) doubles as the P a-frag after in-place exp
__device__ __forceinline__ void mma16816_f16(uint32_t c[2], const uint32_t a[4], const uint32_t b[2]) {
    asm volatile("mma.sync.aligned.m16n8k16.row.col.f16.f16.f16.f16 "
        "{%0,%1}, {%2,%3,%4,%5}, {%6,%7}, {%0,%1};"
        : "+r"(c[0]), "+r"(c[1])
        : "r"(a[0]), "r"(a[1]), "r"(a[2]), "r"(a[3]), "r"(b[0]), "r"(b[1]));
}
__device__ __forceinline__ void ldsm_x4(uint32_t d[4], uint32_t addr) {
    asm volatile("ldmatrix.sync.aligned.m8n8.x4.shared.b16 {%0,%1,%2,%3}, [%4];"
        : "=r"(d[0]), "=r"(d[1]), "=r"(d[2]), "=r"(d[3]) : "r"(addr));
}
__device__ __forceinline__ void cp16(uint32_t sdst, const void* gsrc) {
    asm volatile("cp.async.cg.shared.global [%0], [%1], 16;" :: "r"(sdst), "l"(gsrc));
}
#define CP_COMMIT() asm volatile("cp.async.commit_group;" ::: "memory")
#define CP_WAIT(n)  asm volatile("cp.async.wait_group %0;" :: "n"(n) : "memory")

// ---------------- kernel 1: merged prep (x-convert + transposes + bias + out-init) ----------------
// grid = 1024 (x, 16 elems/thread) + 352 (transpose) + 1 (bias) + 512 (out init) = 1889 blocks.
__global__ __launch_bounds__(256) void prep2_kernel(
    const float* __restrict__ x,
    const float* __restrict__ Wk, const float* __restrict__ bk,
    const float* __restrict__ Wv, const float* __restrict__ bv,
    const float* __restrict__ Wq, const float* __restrict__ bq,
    const float* __restrict__ Wp, const float* __restrict__ bp,
    float* __restrict__ out)
{
    const int bid = blockIdx.x;
    const int tid = threadIdx.x;

    if (bid < 1024) {
        // x -> fp16, 16 elements per thread: 4 front-batched LDG.128 + 2 STG.128
        size_t idx = ((size_t)bid * 256 + tid) * 16;
        float4 a0 = *(const float4*)(x + idx);
        float4 a1 = *(const float4*)(x + idx + 4);
        float4 a2 = *(const float4*)(x + idx + 8);
        float4 a3 = *(const float4*)(x + idx + 12);
        __half2 h0[4] = { __floats2half2_rn(a0.x, a0.y), __floats2half2_rn(a0.z, a0.w),
                          __floats2half2_rn(a1.x, a1.y), __floats2half2_rn(a1.z, a1.w) };
        __half2 h1[4] = { __floats2half2_rn(a2.x, a2.y), __floats2half2_rn(a2.z, a2.w),
                          __floats2half2_rn(a3.x, a3.y), __floats2half2_rn(a3.z, a3.w) };
        *(uint4*)(g_xh + idx)     = *(uint4*)&h0[0];
        *(uint4*)(g_xh + idx + 8) = *(uint4*)&h1[0];
        return;
    }
    if (bid < 1024 + 352) {
        // weight transpose: slab of [512 k][64 n] -> fp16 [n][k]
        __shared__ float t[32][33];
        int bid2 = bid - 1024;
        int slab = bid2 >> 5, tt = bid2 & 31;
        int k0 = (tt & 15) * 32, n0 = (tt >> 4) * 32;
        const float* src;
        __half* dst;
        if (slab == 0)      src = Wk;
        else if (slab == 1) src = Wv;
        else if (slab < 10) src = Wq + (size_t)(slab-2)*WRD*HD;
        else                src = Wp;
        dst = (slab < 10) ? (g_WhT + (size_t)slab*64*WRD) : g_WpT;

        int tx = tid & 31, ty = tid >> 5;   // 32 x 8
        #pragma unroll
        for (int r = 0; r < 4; r++)
            t[ty + r*8][tx] = src[(size_t)(k0 + ty + r*8)*HD + n0 + tx];
        __syncthreads();
        #pragma unroll
        for (int r = 0; r < 4; r++) {
            int n = ty + r*8;
            dst[(size_t)(n0 + n)*WRD + k0 + tx] = __float2half_rn(t[tx][n]);
        }
        return;
    }
    if (bid == 1024 + 352) {
        // bias pack
        for (int i = tid; i < NQKV; i += 256) {
            float v;
            if (i < 64)       v = bk[i];
            else if (i < 128) v = bv[i-64];
            else              v = bq[i-128];
            g_ball[i] = v;
        }
        return;
    }
    // out init: out[m][n] = bp[n]  (heads atomically accumulate on top)
    {
        int idx = (bid - 1025 - 352) * 256 + tid;    // float4 index, 131072 total
        int col = (idx & 15) * 4;
        float4 bv4 = *(const float4*)(bp + col);
        *(float4*)(out + (size_t)idx*4) = bv4;
    }
}

// ---------------- kernel 2: QKV projection, m32 warp tiles, cp.async double-buffered ----------------
// grid (64, 10), 128 thr (4 warps x 32 m-rows). Tile 128m x 64n, K-step 64. 48KB static smem.
__global__ __launch_bounds__(128) void qkv_mma_kernel()
{
    __shared__ __align__(128) char sA[2][128*128];   // 2 x 16KB
    __shared__ __align__(128) char sB[2][64*128];    // 2 x  8KB

    const int tid = threadIdx.x;
    const int wid = tid >> 5, lane = tid & 31;
    const int m0 = blockIdx.x * 128, n0 = blockIdx.y * 64;

    auto load_tiles = [&](int buf, int k0) {
        #pragma unroll
        for (int r = 0; r < 8; r++) {
            int i = tid + r*128;
            int row = i >> 3, c8 = (i & 7) * 8;
            cp16(smem_u32(sA[buf]) + SW128((uint32_t)(row*128 + c8*2)),
                 g_xh + (size_t)(m0 + row)*WRD + k0 + c8);
        }
        #pragma unroll
        for (int r = 0; r < 4; r++) {
            int i = tid + r*128;
            int row = i >> 3, c8 = (i & 7) * 8;
            cp16(smem_u32(sB[buf]) + SW128((uint32_t)(row*128 + c8*2)),
                 g_WhT + (size_t)(n0 + row)*WRD + k0 + c8);
        }
    };

    float acc[2][8][4] = {};
    const uint32_t colb = (uint32_t)((lane & 8) ? 16 : 0);
    const uint32_t rwb  = (uint32_t)(((lane & 16) ? 8 : 0) + (lane & 7));

    load_tiles(0, 0); CP_COMMIT();

    for (int ki = 0; ki < 8; ki++) {
        if (ki < 7) { load_tiles((ki+1)&1, (ki+1)*64); CP_COMMIT(); CP_WAIT(1); }
        else CP_WAIT(0);
        __syncthreads();

        const uint32_t ab = smem_u32(sA[ki&1]), bb = smem_u32(sB[ki&1]);
        #pragma unroll
        for (int kk = 0; kk < 4; kk++) {
            uint32_t afr[2][4];
            #pragma unroll
            for (int a = 0; a < 2; a++) {
                int row = wid*32 + a*16 + (lane & 7) + ((lane >> 3) & 1) * 8;
                uint32_t col = (uint32_t)(kk*32 + ((lane >> 4) ? 16 : 0));
                ldsm_x4(afr[a], ab + SW128((uint32_t)row*128 + col));
            }
            uint32_t cc = (uint32_t)(kk*32) + colb;
            #pragma unroll
            for (int j2 = 0; j2 < 4; j2++) {
                uint32_t bfr[4];
                ldsm_x4(bfr, bb + SW128((j2*16 + rwb)*128 + cc));
                #pragma unroll
                for (int a = 0; a < 2; a++) {
                    mma16816(acc[a][2*j2],   afr[a], bfr);
                    mma16816(acc[a][2*j2+1], afr[a], bfr + 2);
                }
            }
        }
        __syncthreads();
    }

    // ---- epilogue: bias + scatter to K / V^T / Q ----
    #pragma unroll
    for (int a = 0; a < 2; a++) {
        int r = wid*32 + a*16 + (lane >> 2);
        #pragma unroll
        for (int j = 0; j < 8; j++) {
            #pragma unroll
            for (int e = 0; e < 2; e++) {
                int n = n0 + j*8 + (lane & 3)*2 + e;
                float bias = g_ball[n];
                #pragma unroll
                for (int rr = 0; rr < 2; rr++) {
                    int m = m0 + r + rr*8;
                    float v = acc[a][j][rr*2 + e] + bias;
                    int b = m >> 12, s = m & 4095;
                    if (n < 64) {
                        g_Kh[((size_t)b*SEQ + s)*HD + n] = __float2half_rn(v);
                    } else if (n < 128) {
                        g_Vth[((size_t)b*HD + (n-64))*SEQ + s] = __float2half_rn(v);
                    } else {
                        int nn = n - 128; int h = nn >> 6, d = nn & 63;
                        g_Qh[(((size_t)b*NH + h)*SEQ + s)*HD + d] = __float2half_rn(v * QSCALE);
                    }
                }
            }
        }
    }
}

// ---------------- kernel 3: flash attention + fused output projection ----------------
// grid (SEQ/128, NH, BATCH), 128 threads = 4 warps x 32 q-rows, 2 CTAs/SM.
// Mainloop: round-13 config + exp-one-group-ahead pipeline in the tt loop.
// Epilogue: Wp slice prefetched during the last mainloop step; O normalized into fp16
// a-frags, projected, atomicAdd into out (bias pre-added by prep2).
__global__ __launch_bounds__(128, 2) void attn_mma_kernel(float* __restrict__ out)
{
    extern __shared__ __align__(128) char smemAll[];   // 3 x 32768; slot2 doubles as Q staging

    const int tid  = threadIdx.x;
    const int wid  = tid >> 5, lane = tid & 31;
    const int b = blockIdx.z, hh = blockIdx.y, q0 = blockIdx.x * 128;

    const __half* Qp = g_Qh + ((size_t)(b*NH + hh)*SEQ + q0) * HD;
    const __half* Kp = g_Kh  + (size_t)b*SEQ*HD;
    const __half* Vp = g_Vth + (size_t)b*HD*SEQ;

    auto kbuf = [&](int r) -> char* { return smemAll + r*32768; };
    auto vbuf = [&](int r) -> char* { return smemAll + r*32768 + 16384; };
    char* sQ = smemAll + 2*32768;

    auto load_kv = [&](int slot, int kt) {
        char* kb = kbuf(slot); char* vb = vbuf(slot);
        #pragma unroll
        for (int r = 0; r < 8; r++) {
            int i = tid + r*128;
            int row = i >> 3, c8 = (i & 7) * 8;
            cp16(smem_u32(kb) + SW128((uint32_t)(row*128 + c8*2)),
                 Kp + (size_t)(kt*128 + row)*HD + c8);
        }
        #pragma unroll
        for (int r = 0; r < 8; r++) {
            int i = tid + r*128;
            int d = i >> 4, t16 = (i & 15) * 8;
            int sub = t16 >> 6, tloc = t16 & 63;
            cp16(smem_u32(vb) + (uint32_t)(sub*8192) + SW128((uint32_t)(d*128 + tloc*2)),
                 Vp + (size_t)d*SEQ + kt*128 + t16);
        }
    };

    load_kv(0, 0); CP_COMMIT();
    load_kv(1, 1); CP_COMMIT();

    #pragma unroll
    for (int r = 0; r < 8; r++) {
        int i = tid + r*128;
        int row = i >> 3, c8 = (i & 7) * 8;
        *(uint4*)(sQ + SW128((uint32_t)(row*128 + c8*2))) = *(const uint4*)(Qp + row*HD + c8);
    }
    __syncthreads();
    uint32_t qa[2][4][4];
    {
        const uint32_t qb = smem_u32(sQ);
        #pragma unroll
        for (int a = 0; a < 2; a++) {
            int row = wid*32 + a*16 + (lane & 7) + ((lane >> 3) & 1) * 8;
            #pragma unroll
            for (int kk = 0; kk < 4; kk++) {
                uint32_t col = (uint32_t)(kk*32 + ((lane >> 4) ? 16 : 0));
                ldsm_x4(qa[a][kk], qb + SW128((uint32_t)row*128 + col));
            }
        }
    }

    float oc[2][8][4] = {};
    float lsacc[2][4] = {};
    const uint32_t ones_frag[2] = { 0x3C003C00u, 0x3C003C00u };  // fp16 1.0 x4
    const uint32_t colb = (uint32_t)((lane & 8) ? 16 : 0);
    const uint32_t rwb  = (uint32_t)(((lane & 16) ? 8 : 0) + (lane & 7));

    for (int kt = 0; kt < NKT2; kt++) {
        CP_WAIT(0);
        __syncthreads();
        if (kt + 2 < NKT2) { load_kv((kt+2)%3, kt+2); CP_COMMIT(); }
        else if (kt == NKT2 - 1) {
            // prefetch Wp slice [64 n][64 k] into slot0 (free: last read at kt-1's step)
            char* sW = kbuf(0);
            #pragma unroll
            for (int r = 0; r < 4; r++) {
                int i = tid + r*128;
                int row = i >> 3, c8 = (i & 7) * 8;
                cp16(smem_u32(sW) + SW128((uint32_t)(row*128 + c8*2)),
                     g_WpT + (size_t)row*WRD + hh*64 + c8);
            }
            CP_COMMIT();
        }

        const uint32_t kb_ = smem_u32(kbuf(kt%3));
        const uint32_t vb_ = smem_u32(vbuf(kt%3));

        uint32_t scf[2][16][2];
        #pragma unroll
        for (int a = 0; a < 2; a++)
            #pragma unroll
            for (int j = 0; j < 16; j++) { scf[a][j][0] = 0u; scf[a][j][1] = 0u; }
        #pragma unroll
        for (int kk = 0; kk < 4; kk++) {
            uint32_t cc = (uint32_t)(kk*32) + colb;
            #pragma unroll
            for (int j2 = 0; j2 < 8; j2++) {
                uint32_t bfr[4];
                ldsm_x4(bfr, kb_ + SW128((uint32_t)(j2*16 + rwb)*128 + cc));
                #pragma unroll
                for (int a = 0; a < 2; a++) {
                    mma16816_f16(scf[a][2*j2],   qa[a][kk], bfr);
                    mma16816_f16(scf[a][2*j2+1], qa[a][kk], bfr + 2);
                }
            }
        }

        // ---- exp one group ahead of PV: PV(tt) never waits on its own MUFU chain ----
        uint32_t paC[2][4], paN[2][4];
        #pragma unroll
        for (int a = 0; a < 2; a++) {
            __half2 e0 = h2exp2(*(__half2*)&scf[a][0][0]);
            __half2 e1 = h2exp2(*(__half2*)&scf[a][0][1]);
            __half2 e2 = h2exp2(*(__half2*)&scf[a][1][0]);
            __half2 e3 = h2exp2(*(__half2*)&scf[a][1][1]);
            paC[a][0] = *(uint32_t*)&e0; paC[a][1] = *(uint32_t*)&e1;
            paC[a][2] = *(uint32_t*)&e2; paC[a][3] = *(uint32_t*)&e3;
        }
        #pragma unroll
        for (int tt = 0; tt < 8; tt++) {
            if (tt < 7) {
                #pragma unroll
                for (int a = 0; a < 2; a++) {
                    __half2 e0 = h2exp2(*(__half2*)&scf[a][2*tt+2][0]);
                    __half2 e1 = h2exp2(*(__half2*)&scf[a][2*tt+2][1]);
                    __half2 e2 = h2exp2(*(__half2*)&scf[a][2*tt+3][0]);
                    __half2 e3 = h2exp2(*(__half2*)&scf[a][2*tt+3][1]);
                    paN[a][0] = *(uint32_t*)&e0; paN[a][1] = *(uint32_t*)&e1;
                    paN[a][2] = *(uint32_t*)&e2; paN[a][3] = *(uint32_t*)&e3;
                }
            }
            uint32_t vblk = vb_ + (uint32_t)((tt >> 2)*8192);
            uint32_t cc = (uint32_t)((tt & 3)*32) + colb;
            #pragma unroll
            for (int jv = 0; jv < 4; jv++) {
                uint32_t bfr[4];
                ldsm_x4(bfr, vblk + SW128((uint32_t)(jv*16 + rwb)*128 + cc));
                #pragma unroll
                for (int a = 0; a < 2; a++) {
                    mma16816(oc[a][2*jv],   paC[a], bfr);
                    mma16816(oc[a][2*jv+1], paC[a], bfr + 2);
                }
            }
            #pragma unroll
            for (int a = 0; a < 2; a++) {
                mma16816(lsacc[a], paC[a], ones_frag);
                paC[a][0] = paN[a][0]; paC[a][1] = paN[a][1];
                paC[a][2] = paN[a][2]; paC[a][3] = paN[a][3];
            }
        }
    }

    // ---- fused output projection: out += (O/lsum) @ WpT[., hh*64 : hh*64+64] ----
    CP_WAIT(0);
    __syncthreads();
    {
        const uint32_t wb_ = smem_u32(kbuf(0));
        float outacc[2][8][4] = {};
        #pragma unroll
        for (int a = 0; a < 2; a++) {
            float inv0 = 1.0f / lsacc[a][0], inv1 = 1.0f / lsacc[a][2];
            #pragma unroll
            for (int kk = 0; kk < 4; kk++) {
                uint32_t oa[4];
                __half2 h0 = __floats2half2_rn(oc[a][2*kk][0]*inv0,   oc[a][2*kk][1]*inv0);
                __half2 h1 = __floats2half2_rn(oc[a][2*kk][2]*inv1,   oc[a][2*kk][3]*inv1);
                __half2 h2_ = __floats2half2_rn(oc[a][2*kk+1][0]*inv0, oc[a][2*kk+1][1]*inv0);
                __half2 h3 = __floats2half2_rn(oc[a][2*kk+1][2]*inv1, oc[a][2*kk+1][3]*inv1);
                oa[0] = *(uint32_t*)&h0;
                oa[1] = *(uint32_t*)&h1;
                oa[2] = *(uint32_t*)&h2_;
                oa[3] = *(uint32_t*)&h3;
                uint32_t cc = (uint32_t)(kk*32) + colb;
                #pragma unroll
                for (int j2 = 0; j2 < 4; j2++) {
                    uint32_t bfr[4];
                    ldsm_x4(bfr, wb_ + SW128((uint32_t)(j2*16 + rwb)*128 + cc));
                    mma16816(outacc[a][2*j2],   oa, bfr);
                    mma16816(outacc[a][2*j2+1], oa, bfr + 2);
                }
            }
        }

        int c0 = (lane & 3) * 2;
        #pragma unroll
        for (int a = 0; a < 2; a++) {
            int r = wid*32 + a*16 + (lane >> 2);
            float* O0 = out + ((size_t)(b*SEQ) + q0 + r    )*HD;
            float* O1 = out + ((size_t)(b*SEQ) + q0 + r + 8)*HD;
            #pragma unroll
            for (int j = 0; j < 8; j++) {
                int n = j*8 + c0;
                atomicAdd(O0 + n,     outacc[a][j][0]);
                atomicAdd(O0 + n + 1, outacc[a][j][1]);
                atomicAdd(O1 + n,     outacc[a][j][2]);
                atomicAdd(O1 + n + 1, outacc[a][j][3]);
            }
        }
    }
}

// ---------------- launch ----------------
extern "C" void kernel_launch(void* const* d_in, const int* in_sizes, int n_in,
                              void* d_out, int out_size)
{
    const float* x  = (const float*)d_in[0];
    const float* Wq = (const float*)d_in[1];
    const float* bq = (const float*)d_in[2];
    const float* Wk = (const float*)d_in[3];
    const float* bk = (const float*)d_in[4];
    const float* Wv = (const float*)d_in[5];
    const float* bv = (const float*)d_in[6];
    const float* Wp = (const float*)d_in[7];
    const float* bp = (const float*)d_in[8];
    float* out = (float*)d_out;

    prep2_kernel<<<1024 + 352 + 1 + 512, 256>>>(x, Wk, bk, Wv, bv, Wq, bq, Wp, bp, out);

    qkv_mma_kernel<<<dim3(MTOT/128, NQKV/64), 128>>>();

    const int attn_smem = 3 * 32768;   // 96KB dynamic ring
    cudaFuncSetAttribute(attn_mma_kernel, cudaFuncAttributeMaxDynamicSharedMemorySize, attn_smem);
    attn_mma_kernel<<<dim3(SEQ/128, NH, BATCH), 128, attn_smem>>>(out);
}